// round 1
// baseline (speedup 1.0000x reference)
#include <cuda_runtime.h>
#include <cstdint>

#define NPTS 4096
#define NTH  1024

// d_out float32 layout (concat of reference return tuple, C-order):
//   Pc    [4][2][4096][3]  @ 0
//   Tc    [4][2][4096][3]  @ 98304
//   keepP [4][2][4096]     @ 196608
//   keepT [4][2][4096]     @ 229376
//   tp    [4][2][4096]     @ 262144
//   fp    [4][2][4096]     @ 294912
//   fn    [4][2][4096]     @ 327680
#define OFF_TC 98304
#define OFF_KP 196608
#define OFF_KT 229376
#define OFF_TP 262144
#define OFF_FP 294912
#define OFF_FN 327680

__device__ __forceinline__ float dist2(float ax, float ay, float az,
                                       float bx, float by, float bz) {
    float dx = __fadd_rn(ax, -bx);
    float dy = __fadd_rn(ay, -by);
    float dz = __fadd_rn(az, -bz);
    return __fadd_rn(__fadd_rn(__fmul_rn(dx, dx), __fmul_rn(dy, dy)),
                     __fmul_rn(dz, dz));
}

// ---------------------------------------------------------------------------
// Kernel 1: per (tensor, b, e): transform -> sort desc by conf -> NMS
// 16 blocks of 1024 threads.
// ---------------------------------------------------------------------------
__global__ void __launch_bounds__(1024) k_sort_nms(const float* __restrict__ pred,
                                                   const float* __restrict__ targ,
                                                   float* __restrict__ out)
{
    extern __shared__ unsigned char sm[];
    unsigned long long* key = (unsigned long long*)sm;            // [4096] 32KB (phase A)
    float* cx = (float*)sm;                                       // alias (phase B)
    float* cy = cx + 4096;
    float* cz = (float*)(sm + 32 * 1024);                         // 16KB
    unsigned short* spos = (unsigned short*)(sm + 48 * 1024);     // 8KB
    unsigned char* keepc = (unsigned char*)(sm + 56 * 1024);      // 4KB
    unsigned char* fullk = (unsigned char*)(sm + 60 * 1024);      // 4KB
    unsigned long long* mat = (unsigned long long*)(sm + 64 * 1024); // [64] 512B

    __shared__ int wsum[32];
    __shared__ unsigned long long supp;

    const int tid = threadIdx.x;
    const int bi = blockIdx.x;
    const int t = bi >> 3;           // 0 = predictions, 1 = targets
    const int be = bi & 7;
    const int b = be >> 1;
    const int e = be & 1;
    const float* in = (t == 0) ? pred : targ;
    const float de = (e == 0) ? (float)(0.74 * 1.4) : (float)(0.528 * 1.4);
    const float dd = __fmul_rn(de, de);

    // ---- Phase A: sortable keys (conf descending, index ascending tiebreak) ----
    for (int q = 0; q < 4; q++) {
        int n = tid * 4 + q;
        int z = n >> 10, x = (n >> 5) & 31, y = n & 31;
        int base = ((((b * 32 + x) * 32 + y) * 4 + z) * 8) + e * 4;
        float conf = in[base + 3];
        unsigned u = __float_as_uint(conf);
        u = (u & 0x80000000u) ? ~u : (u | 0x80000000u);   // ascending-order map
        key[n] = (((unsigned long long)(~u)) << 32) | (unsigned)n;
    }
    __syncthreads();

    // ---- Bitonic sort ascending on u64 keys ----
    for (int k = 2; k <= NPTS; k <<= 1) {
        for (int j = k >> 1; j > 0; j >>= 1) {
            for (int q = 0; q < 4; q++) {
                int i = tid + q * 1024;
                int ixj = i ^ j;
                if (ixj > i) {
                    bool up = ((i & k) == 0);
                    unsigned long long a = key[i], c = key[ixj];
                    if ((a > c) == up) { key[i] = c; key[ixj] = a; }
                }
            }
            __syncthreads();
        }
    }

    // ---- Phase B: coords for sorted positions, write Pc/Tc, compact valid ----
    unsigned long long myk[4];
    for (int q = 0; q < 4; q++) myk[q] = key[tid * 4 + q];

    float rx[4], ry[4], rz[4];
    int vflag[4];
    int cnt = 0;
    for (int q = 0; q < 4; q++) {
        int n = (int)(myk[q] & 0xFFFFFFFFull);
        int z = n >> 10, x = (n >> 5) & 31, y = n & 31;
        int base = ((((b * 32 + x) * 32 + y) * 4 + z) * 8) + e * 4;
        float4 v = *(const float4*)(in + base);
        float c0 = __fmul_rn(__fadd_rn(v.z, (float)z), 0.75f);
        float c1 = __fmul_rn(__fadd_rn(v.x, (float)x), 0.78125f);
        float c2 = __fmul_rn(__fadd_rn(v.y, (float)y), 0.78125f);
        rx[q] = c0; ry[q] = c1; rz[q] = c2;
        vflag[q] = (v.w > 0.5f) ? 1 : 0;
        cnt += vflag[q];
        int s = tid * 4 + q;
        int ob = (t ? OFF_TC : 0) + ((b * 2 + e) * 4096 + s) * 3;
        out[ob + 0] = c0; out[ob + 1] = c1; out[ob + 2] = c2;
    }

    // block scan over per-thread counts
    int lane = tid & 31, wid = tid >> 5;
    int v = cnt;
    for (int o = 1; o < 32; o <<= 1) {
        int nn = __shfl_up_sync(0xFFFFFFFFu, v, o);
        if (lane >= o) v += nn;
    }
    if (lane == 31) wsum[wid] = v;
    __syncthreads();   // also guarantees all key reads done before aliased writes
    if (wid == 0) {
        int w = wsum[lane];
        for (int o = 1; o < 32; o <<= 1) {
            int nn = __shfl_up_sync(0xFFFFFFFFu, w, o);
            if (lane >= o) w += nn;
        }
        wsum[lane] = w;
    }
    __syncthreads();
    int excl = v - cnt + (wid ? wsum[wid - 1] : 0);
    int m = wsum[31];

    for (int q = 0; q < 4; q++) {
        if (vflag[q]) {
            cx[excl] = rx[q]; cy[excl] = ry[q]; cz[excl] = rz[q];
            spos[excl] = (unsigned short)(tid * 4 + q);
            excl++;
        }
    }
    __syncthreads();

    // ---- Chunked greedy NMS over compacted valid points (sorted order) ----
    int nchunks = (m + 63) >> 6;
    for (int c = 0; c < nchunks; c++) {
        int cb = c * 64;
        int cc = min(64, m - cb);
        if (tid == 0) supp = 0ull;
        if (tid < 64) mat[tid] = 0ull;
        __syncthreads();

        // suppression from already-finalized earlier points
        unsigned long long mysup = 0ull;
        for (int p = tid; p < cb; p += NTH) {
            if (keepc[p]) {
                float px = cx[p], py = cy[p], pz = cz[p];
                for (int j = 0; j < cc; j++) {
                    float d2 = dist2(px, py, pz, cx[cb + j], cy[cb + j], cz[cb + j]);
                    if (d2 < dd) mysup |= (1ull << j);
                }
            }
        }
        if (mysup) atomicOr(&supp, mysup);

        // intra-chunk pairwise matrix (i suppresses j, i < j)
        for (int id = tid; id < 64 * 64; id += NTH) {
            int i = id >> 6, j = id & 63;
            if (i < j && j < cc) {
                float d2 = dist2(cx[cb + i], cy[cb + i], cz[cb + i],
                                 cx[cb + j], cy[cb + j], cz[cb + j]);
                if (d2 < dd) atomicOr(&mat[i], 1ull << j);
            }
        }
        __syncthreads();

        if (tid == 0) {
            unsigned long long s = supp;
            for (int j = 0; j < cc; j++) {
                if ((s >> j) & 1ull) keepc[cb + j] = 0;
                else { keepc[cb + j] = 1; s |= mat[j]; }
            }
        }
        __syncthreads();
    }

    // ---- scatter keep back to sorted positions, write float mask ----
    for (int q = 0; q < 4; q++) fullk[tid * 4 + q] = 0;
    __syncthreads();
    for (int ci = tid; ci < m; ci += NTH) fullk[spos[ci]] = keepc[ci];
    __syncthreads();
    int kb = (t ? OFF_KT : OFF_KP) + (b * 2 + e) * 4096;
    for (int q = 0; q < 4; q++) {
        int s = tid * 4 + q;
        out[kb + s] = (float)fullk[s];
    }
}

// ---------------------------------------------------------------------------
// Kernel 2: per (b, e): greedy row-major bipartite matching -> tp/fp/fn
// 8 blocks of 1024 threads. Reads Pc/Tc/keepP/keepT from d_out.
// ---------------------------------------------------------------------------
__global__ void __launch_bounds__(1024) k_match(float* __restrict__ out)
{
    extern __shared__ unsigned char sm[];
    float* cpx = (float*)sm;
    float* cpy = cpx + 4096;
    float* cpz = cpy + 4096;
    float* ctx = cpz + 4096;
    float* cty = ctx + 4096;
    float* ctz = cty + 4096;                                       // ..96KB
    unsigned short* ppos = (unsigned short*)(sm + 96 * 1024);      // 8KB
    unsigned short* tpos = (unsigned short*)(sm + 104 * 1024);     // 8KB
    unsigned long long* mat = (unsigned long long*)(sm + 112 * 1024); // [64*64] 32KB
    unsigned char* tpF = (unsigned char*)(sm + 144 * 1024);        // 4KB
    unsigned char* mtF = (unsigned char*)(sm + 148 * 1024);        // 4KB
    unsigned long long* taken = (unsigned long long*)(sm + 152 * 1024); // [64]

    __shared__ int wsum[32];
    __shared__ int cntP, cntT;

    const int tid = threadIdx.x;
    const int be = blockIdx.x;
    const int b = be >> 1, e = be & 1;
    const float de = (e == 0) ? (float)(0.74 * 1.4) : (float)(0.528 * 1.4);
    const float dd = __fmul_rn(de, de);

    const int pcBase = (b * 2 + e) * 4096 * 3;
    const int tcBase = OFF_TC + pcBase;
    const int kpBase = OFF_KP + (b * 2 + e) * 4096;
    const int ktBase = OFF_KT + (b * 2 + e) * 4096;

    const int lane = tid & 31, wid = tid >> 5;

    // ---- compact kept preds ----
    {
        float rx[4], ry[4], rz[4]; int f[4]; int cnt = 0;
        for (int q = 0; q < 4; q++) {
            int s = tid * 4 + q;
            int kp = (out[kpBase + s] > 0.5f) ? 1 : 0;
            f[q] = kp; cnt += kp;
            if (kp) {
                rx[q] = out[pcBase + s * 3 + 0];
                ry[q] = out[pcBase + s * 3 + 1];
                rz[q] = out[pcBase + s * 3 + 2];
            }
        }
        int v = cnt;
        for (int o = 1; o < 32; o <<= 1) {
            int nn = __shfl_up_sync(0xFFFFFFFFu, v, o);
            if (lane >= o) v += nn;
        }
        if (lane == 31) wsum[wid] = v;
        __syncthreads();
        if (wid == 0) {
            int w = wsum[lane];
            for (int o = 1; o < 32; o <<= 1) {
                int nn = __shfl_up_sync(0xFFFFFFFFu, w, o);
                if (lane >= o) w += nn;
            }
            wsum[lane] = w;
        }
        __syncthreads();
        int excl = v - cnt + (wid ? wsum[wid - 1] : 0);
        if (tid == 0) cntP = wsum[31];
        for (int q = 0; q < 4; q++) {
            if (f[q]) {
                cpx[excl] = rx[q]; cpy[excl] = ry[q]; cpz[excl] = rz[q];
                ppos[excl] = (unsigned short)(tid * 4 + q);
                excl++;
            }
        }
        __syncthreads();
    }

    // ---- compact kept targets ----
    {
        float rx[4], ry[4], rz[4]; int f[4]; int cnt = 0;
        for (int q = 0; q < 4; q++) {
            int s = tid * 4 + q;
            int kt = (out[ktBase + s] > 0.5f) ? 1 : 0;
            f[q] = kt; cnt += kt;
            if (kt) {
                rx[q] = out[tcBase + s * 3 + 0];
                ry[q] = out[tcBase + s * 3 + 1];
                rz[q] = out[tcBase + s * 3 + 2];
            }
        }
        int v = cnt;
        for (int o = 1; o < 32; o <<= 1) {
            int nn = __shfl_up_sync(0xFFFFFFFFu, v, o);
            if (lane >= o) v += nn;
        }
        if (lane == 31) wsum[wid] = v;
        __syncthreads();
        if (wid == 0) {
            int w = wsum[lane];
            for (int o = 1; o < 32; o <<= 1) {
                int nn = __shfl_up_sync(0xFFFFFFFFu, w, o);
                if (lane >= o) w += nn;
            }
            wsum[lane] = w;
        }
        __syncthreads();
        int excl = v - cnt + (wid ? wsum[wid - 1] : 0);
        if (tid == 0) cntT = wsum[31];
        for (int q = 0; q < 4; q++) {
            if (f[q]) {
                ctx[excl] = rx[q]; cty[excl] = ry[q]; ctz[excl] = rz[q];
                tpos[excl] = (unsigned short)(tid * 4 + q);
                excl++;
            }
        }
    }

    if (tid < 64) taken[tid] = 0ull;
    for (int q = 0; q < 4; q++) { tpF[tid * 4 + q] = 0; mtF[tid * 4 + q] = 0; }
    __syncthreads();

    const int KP = cntP, KT = cntT;
    const int nw = (KT + 63) >> 6;            // <= 64 words
    const int nchunks = (KP + 63) >> 6;

    for (int c = 0; c < nchunks; c++) {
        int cb = c * 64;
        int cc = min(64, KP - cb);

        // build candidate bit matrix: row i (pred cb+i), word w covers targets w*64..
        for (int id = tid; id < cc * nw; id += NTH) {
            int i = id / nw, w = id % nw;
            float px = cpx[cb + i], py = cpy[cb + i], pz = cpz[cb + i];
            unsigned long long bits = 0ull;
            int jb = w * 64;
            int je = min(64, KT - jb);
            for (int jj = 0; jj < je; jj++) {
                float d2 = dist2(px, py, pz, ctx[jb + jj], cty[jb + jj], ctz[jb + jj]);
                if (d2 < dd) bits |= (1ull << jj);
            }
            mat[i * 64 + w] = bits;
        }
        __syncthreads();

        // warp 0: sequential greedy resolution, ballots across 64-bit words
        if (tid < 32) {
            int ln = tid;
            for (int i = 0; i < cc; i++) {
                unsigned long long a0 = (ln < nw) ? (mat[i * 64 + ln] & ~taken[ln]) : 0ull;
                unsigned long long a1 = (ln + 32 < nw) ? (mat[i * 64 + ln + 32] & ~taken[ln + 32]) : 0ull;
                unsigned b0 = __ballot_sync(0xFFFFFFFFu, a0 != 0ull);
                unsigned b1 = __ballot_sync(0xFFFFFFFFu, a1 != 0ull);
                int w = -1;
                if (b0) w = __ffs(b0) - 1;
                else if (b1) w = 32 + __ffs(b1) - 1;
                if (w >= 0 && ln == (w & 31)) {
                    unsigned long long a = (w < 32) ? a0 : a1;
                    int bit = __ffsll((long long)a) - 1;
                    taken[w] |= (1ull << bit);
                    int j = w * 64 + bit;
                    mtF[tpos[j]] = 1;
                    tpF[ppos[cb + i]] = 1;
                }
                __syncwarp(0xFFFFFFFFu);
            }
        }
        __syncthreads();
    }

    // ---- write tp / fp / fn ----
    const int tpB = OFF_TP + (b * 2 + e) * 4096;
    const int fpB = OFF_FP + (b * 2 + e) * 4096;
    const int fnB = OFF_FN + (b * 2 + e) * 4096;
    for (int q = 0; q < 4; q++) {
        int s = tid * 4 + q;
        int tp = tpF[s];
        int kp = (out[kpBase + s] > 0.5f) ? 1 : 0;
        int kt = (out[ktBase + s] > 0.5f) ? 1 : 0;
        out[tpB + s] = (float)tp;
        out[fpB + s] = (kp && !tp) ? 1.0f : 0.0f;
        out[fnB + s] = (kt && !mtF[s]) ? 1.0f : 0.0f;
    }
}

// ---------------------------------------------------------------------------
extern "C" void kernel_launch(void* const* d_in, const int* in_sizes, int n_in,
                              void* d_out, int out_size)
{
    const float* pred = (const float*)d_in[0];
    const float* targ = (const float*)d_in[1];
    float* out = (float*)d_out;

    cudaFuncSetAttribute(k_sort_nms, cudaFuncAttributeMaxDynamicSharedMemorySize, 68 * 1024);
    cudaFuncSetAttribute(k_match, cudaFuncAttributeMaxDynamicSharedMemorySize, 160 * 1024);

    k_sort_nms<<<16, NTH, 68 * 1024>>>(pred, targ, out);
    k_match<<<8, NTH, 160 * 1024>>>(out);
}

// round 2
// speedup vs baseline: 2.2361x; 2.2361x over previous
#include <cuda_runtime.h>
#include <cstdint>

#define NPTS 4096
#define NTH  1024

// d_out float32 layout:
//   Pc [4][2][4096][3] @0, Tc @98304, keepP @196608, keepT @229376,
//   tp @262144, fp @294912, fn @327680
#define OFF_TC 98304
#define OFF_KP 196608
#define OFF_KT 229376
#define OFF_TP 262144
#define OFF_FP 294912
#define OFF_FN 327680

// spatial hash: 32 x 32 x 8 bins, clamped
#define NBX 32
#define NBZ 8

__device__ __forceinline__ float dist2(float ax, float ay, float az,
                                       float bx, float by, float bz) {
    float dx = __fadd_rn(ax, -bx);
    float dy = __fadd_rn(ay, -by);
    float dz = __fadd_rn(az, -bz);
    return __fadd_rn(__fadd_rn(__fmul_rn(dx, dx), __fmul_rn(dy, dy)),
                     __fmul_rn(dz, dz));
}

__device__ __forceinline__ int clampi(int v, int lo, int hi) {
    return v < lo ? lo : (v > hi ? hi : v);
}

__device__ __forceinline__ void binCoords(float x, float y, float z,
                                          float invXY, float invZ,
                                          int& bx, int& by, int& bz) {
    bx = clampi((int)floorf(__fmul_rn(__fadd_rn(x, 4.5f), invXY)), 0, NBX - 1);
    by = clampi((int)floorf(__fmul_rn(__fadd_rn(y, 4.5f), invXY)), 0, NBX - 1);
    bz = clampi((int)floorf(__fmul_rn(__fadd_rn(z, 4.0f), invZ)),  0, NBZ - 1);
}

// exclusive block scan over per-thread value; returns exclusive prefix; wsum[31]=total
__device__ __forceinline__ int blockScanExcl(int cnt, int* wsum, int tid) {
    int lane = tid & 31, wid = tid >> 5;
    int v = cnt;
    for (int o = 1; o < 32; o <<= 1) {
        int nn = __shfl_up_sync(0xFFFFFFFFu, v, o);
        if (lane >= o) v += nn;
    }
    if (lane == 31) wsum[wid] = v;
    __syncthreads();
    if (wid == 0) {
        int w = wsum[lane];
        for (int o = 1; o < 32; o <<= 1) {
            int nn = __shfl_up_sync(0xFFFFFFFFu, w, o);
            if (lane >= o) w += nn;
        }
        wsum[lane] = w;
    }
    __syncthreads();
    return v - cnt + (wid ? wsum[wid - 1] : 0);
}

// ---------------------------------------------------------------------------
// Kernel 1: per (tensor, b, e): transform -> sort -> binned NMS. 16 blocks.
// smem layout (bytes):
//  0      key u64[4096] (32KB)  | aliased later: cx f[4096]@0, cy f[4096]@16K
//  32K    cz f[4096] (16KB)
//  48K    spos u16[4096] (8KB)
//  56K    keepc u8[4096] (4KB)
//  60K    fullk u8[4096] (4KB)
//  64K    mat u64[64] (512B)
//  66K    binCnt u32[8192] (32KB)
//  98K    binStart u32[8192] (32KB)
//  130K   binPts u16[4096] (8KB)   -> 138KB
// ---------------------------------------------------------------------------
__global__ void __launch_bounds__(1024) k_sort_nms(const float* __restrict__ pred,
                                                   const float* __restrict__ targ,
                                                   float* __restrict__ out)
{
    extern __shared__ unsigned char sm[];
    unsigned long long* key = (unsigned long long*)sm;
    float* cx = (float*)sm;
    float* cy = cx + 4096;
    float* cz = (float*)(sm + 32 * 1024);
    unsigned short* spos = (unsigned short*)(sm + 48 * 1024);
    unsigned char* keepc = (unsigned char*)(sm + 56 * 1024);
    unsigned char* fullk = (unsigned char*)(sm + 60 * 1024);
    unsigned long long* mat = (unsigned long long*)(sm + 64 * 1024);
    unsigned int* binCnt = (unsigned int*)(sm + 66 * 1024);
    unsigned int* binStart = (unsigned int*)(sm + 98 * 1024);
    unsigned short* binPts = (unsigned short*)(sm + 130 * 1024);

    __shared__ int wsum[32];
    __shared__ unsigned long long supp;

    const int tid = threadIdx.x;
    const int bi = blockIdx.x;
    const int t = bi >> 3;
    const int be = bi & 7;
    const int b = be >> 1;
    const int e = be & 1;
    const float* in = (t == 0) ? pred : targ;
    const float de = (e == 0) ? (float)(0.74 * 1.4) : (float)(0.528 * 1.4);
    const float dd = __fmul_rn(de, de);
    const float cellXY = fmaxf(de, 1.02f);
    const float invXY = 1.0f / cellXY;
    const float invZ = 1.0f / 1.3125f;

    // ---- keys ----
    for (int q = 0; q < 4; q++) {
        int n = tid * 4 + q;
        int z = n >> 10, x = (n >> 5) & 31, y = n & 31;
        int base = ((((b * 32 + x) * 32 + y) * 4 + z) * 8) + e * 4;
        float conf = in[base + 3];
        unsigned u = __float_as_uint(conf);
        u = (u & 0x80000000u) ? ~u : (u | 0x80000000u);
        key[n] = (((unsigned long long)(~u)) << 32) | (unsigned)n;
    }
    __syncthreads();

    // ---- bitonic sort ----
    for (int k = 2; k <= NPTS; k <<= 1) {
        for (int j = k >> 1; j > 0; j >>= 1) {
            for (int q = 0; q < 4; q++) {
                int i = tid + q * 1024;
                int ixj = i ^ j;
                if (ixj > i) {
                    bool up = ((i & k) == 0);
                    unsigned long long a = key[i], c = key[ixj];
                    if ((a > c) == up) { key[i] = c; key[ixj] = a; }
                }
            }
            __syncthreads();
        }
    }

    // ---- coords + write Pc/Tc + compact valid ----
    unsigned long long myk[4];
    for (int q = 0; q < 4; q++) myk[q] = key[tid * 4 + q];

    float rx[4], ry[4], rz[4];
    int vflag[4]; int cnt = 0;
    for (int q = 0; q < 4; q++) {
        int n = (int)(myk[q] & 0xFFFFFFFFull);
        int z = n >> 10, x = (n >> 5) & 31, y = n & 31;
        int base = ((((b * 32 + x) * 32 + y) * 4 + z) * 8) + e * 4;
        float4 v = *(const float4*)(in + base);
        float c0 = __fmul_rn(__fadd_rn(v.z, (float)z), 0.75f);
        float c1 = __fmul_rn(__fadd_rn(v.x, (float)x), 0.78125f);
        float c2 = __fmul_rn(__fadd_rn(v.y, (float)y), 0.78125f);
        rx[q] = c0; ry[q] = c1; rz[q] = c2;
        vflag[q] = (v.w > 0.5f) ? 1 : 0;
        cnt += vflag[q];
        int s = tid * 4 + q;
        int ob = (t ? OFF_TC : 0) + ((b * 2 + e) * 4096 + s) * 3;
        out[ob + 0] = c0; out[ob + 1] = c1; out[ob + 2] = c2;
    }
    __syncthreads();   // all key reads done before aliased writes

    int excl = blockScanExcl(cnt, wsum, tid);
    int m = wsum[31];

    for (int q = 0; q < 4; q++) {
        if (vflag[q]) {
            cx[excl] = rx[q]; cy[excl] = ry[q]; cz[excl] = rz[q];
            spos[excl] = (unsigned short)(tid * 4 + q);
            excl++;
        }
    }
    // zero bin counts
    for (int i = tid; i < NBX * NBX * NBZ; i += NTH) binCnt[i] = 0;
    __syncthreads();

    // ---- build bins over compacted valid points ----
    for (int ci = tid; ci < m; ci += NTH) {
        int bx, by, bz;
        binCoords(cx[ci], cy[ci], cz[ci], invXY, invZ, bx, by, bz);
        atomicAdd(&binCnt[(bz * NBX + by) * NBX + bx], 1u);
    }
    __syncthreads();
    {
        int base8 = tid * 8;
        int loc[8]; int s = 0;
        for (int k2 = 0; k2 < 8; k2++) { loc[k2] = s; s += (int)binCnt[base8 + k2]; }
        int ex = blockScanExcl(s, wsum, tid);
        for (int k2 = 0; k2 < 8; k2++) binStart[base8 + k2] = (unsigned)(ex + loc[k2]);
    }
    __syncthreads();
    for (int i = tid; i < NBX * NBX * NBZ; i += NTH) binCnt[i] = 0;
    __syncthreads();
    for (int ci = tid; ci < m; ci += NTH) {
        int bx, by, bz;
        binCoords(cx[ci], cy[ci], cz[ci], invXY, invZ, bx, by, bz);
        int bb = (bz * NBX + by) * NBX + bx;
        unsigned off = atomicAdd(&binCnt[bb], 1u);
        binPts[binStart[bb] + off] = (unsigned short)ci;
    }
    __syncthreads();

    // ---- chunked greedy NMS with binned neighbor scans ----
    int nchunks = (m + 63) >> 6;
    for (int c = 0; c < nchunks; c++) {
        int cb = c * 64;
        int cc = min(64, m - cb);
        if (tid == 0) supp = 0ull;
        if (tid < 64) mat[tid] = 0ull;
        __syncthreads();

        int jj = tid >> 4, sub = tid & 15;
        if (jj < cc) {
            int j = cb + jj;
            float px = cx[j], py = cy[j], pz = cz[j];
            int bx, by, bz;
            binCoords(px, py, pz, invXY, invZ, bx, by, bz);
            bool suppressed = false;
            for (int nb = sub; nb < 27; nb += 16) {
                int dxb = nb % 3 - 1, dyb = (nb / 3) % 3 - 1, dzb = nb / 9 - 1;
                int X = bx + dxb, Y = by + dyb, Z = bz + dzb;
                if (X < 0 || X >= NBX || Y < 0 || Y >= NBX || Z < 0 || Z >= NBZ) continue;
                int bb = (Z * NBX + Y) * NBX + X;
                unsigned st = binStart[bb], cn = binCnt[bb];
                for (unsigned p = 0; p < cn; p++) {
                    int a = binPts[st + p];
                    if (a >= j) continue;
                    float d2 = dist2(px, py, pz, cx[a], cy[a], cz[a]);
                    if (d2 < dd) {
                        if (a < cb) { if (keepc[a]) suppressed = true; }
                        else atomicOr(&mat[a - cb], 1ull << jj);
                    }
                }
            }
            if (suppressed) atomicOr(&supp, 1ull << jj);
        }
        __syncthreads();

        if (tid == 0) {
            unsigned long long s = supp;
            #pragma unroll
            for (int q = 0; q < 64; q++) {
                unsigned long long mj = mat[q];
                bool kp = !((s >> q) & 1ull);
                if (kp) s |= mj;
                if (q < cc) keepc[cb + q] = kp ? 1 : 0;
            }
        }
        __syncthreads();
    }

    // ---- scatter keep, write mask ----
    for (int q = 0; q < 4; q++) fullk[tid * 4 + q] = 0;
    __syncthreads();
    for (int ci = tid; ci < m; ci += NTH) fullk[spos[ci]] = keepc[ci];
    __syncthreads();
    int kb = (t ? OFF_KT : OFF_KP) + (b * 2 + e) * 4096;
    for (int q = 0; q < 4; q++) {
        int s = tid * 4 + q;
        out[kb + s] = (float)fullk[s];
    }
}

// ---------------------------------------------------------------------------
// Kernel 2: per (b,e) greedy matching via binned candidate lists. 8 blocks.
// smem layout:
//  0    cpx f[2048] 8K ; 8K cpy ; 16K cpz ; 24K ctx ; 32K cty ; 40K ctz
//  48K  ppos u16[2048] ; 52K tpos u16[2048]
//  56K  binCnt u32[8192] 32K ; 88K binStart u32[8192] 32K ; 120K binPts u16[2048] 4K
//  124K candCnt u8[2048] 2K ; 126K cand u16[2048*12] 48K -> 174K
//  174K tpF u8[4096] 4K ; 178K mtF u8[4096] 4K ; 182K taken u32[64] 256B
// ---------------------------------------------------------------------------
#define CAP 12
__global__ void __launch_bounds__(1024) k_match(float* __restrict__ out)
{
    extern __shared__ unsigned char sm[];
    float* cpx = (float*)sm;
    float* cpy = (float*)(sm + 8 * 1024);
    float* cpz = (float*)(sm + 16 * 1024);
    float* ctx = (float*)(sm + 24 * 1024);
    float* cty = (float*)(sm + 32 * 1024);
    float* ctz = (float*)(sm + 40 * 1024);
    unsigned short* ppos = (unsigned short*)(sm + 48 * 1024);
    unsigned short* tpos = (unsigned short*)(sm + 52 * 1024);
    unsigned int* binCnt = (unsigned int*)(sm + 56 * 1024);
    unsigned int* binStart = (unsigned int*)(sm + 88 * 1024);
    unsigned short* binPts = (unsigned short*)(sm + 120 * 1024);
    unsigned char* candCnt = (unsigned char*)(sm + 124 * 1024);
    unsigned short* cand = (unsigned short*)(sm + 126 * 1024);
    unsigned char* tpF = (unsigned char*)(sm + 174 * 1024);
    unsigned char* mtF = (unsigned char*)(sm + 178 * 1024);
    unsigned int* taken = (unsigned int*)(sm + 182 * 1024);

    __shared__ int wsum[32];
    __shared__ int cntP, cntT;

    const int tid = threadIdx.x;
    const int be = blockIdx.x;
    const int b = be >> 1, e = be & 1;
    const float de = (e == 0) ? (float)(0.74 * 1.4) : (float)(0.528 * 1.4);
    const float dd = __fmul_rn(de, de);
    const float cellXY = fmaxf(de, 1.02f);
    const float invXY = 1.0f / cellXY;
    const float invZ = 1.0f / 1.3125f;

    const int pcBase = (b * 2 + e) * 4096 * 3;
    const int tcBase = OFF_TC + pcBase;
    const int kpBase = OFF_KP + (b * 2 + e) * 4096;
    const int ktBase = OFF_KT + (b * 2 + e) * 4096;

    // ---- compact kept preds ----
    {
        float rx[4], ry[4], rz[4]; int f[4]; int cnt = 0;
        for (int q = 0; q < 4; q++) {
            int s = tid * 4 + q;
            int kp = (out[kpBase + s] > 0.5f) ? 1 : 0;
            f[q] = kp; cnt += kp;
            if (kp) {
                rx[q] = out[pcBase + s * 3 + 0];
                ry[q] = out[pcBase + s * 3 + 1];
                rz[q] = out[pcBase + s * 3 + 2];
            }
        }
        int excl = blockScanExcl(cnt, wsum, tid);
        if (tid == 0) cntP = wsum[31];
        for (int q = 0; q < 4; q++) {
            if (f[q] && excl < 2048) {
                cpx[excl] = rx[q]; cpy[excl] = ry[q]; cpz[excl] = rz[q];
                ppos[excl] = (unsigned short)(tid * 4 + q);
                excl++;
            } else if (f[q]) excl++;
        }
        __syncthreads();
    }
    // ---- compact kept targets ----
    {
        float rx[4], ry[4], rz[4]; int f[4]; int cnt = 0;
        for (int q = 0; q < 4; q++) {
            int s = tid * 4 + q;
            int kt = (out[ktBase + s] > 0.5f) ? 1 : 0;
            f[q] = kt; cnt += kt;
            if (kt) {
                rx[q] = out[tcBase + s * 3 + 0];
                ry[q] = out[tcBase + s * 3 + 1];
                rz[q] = out[tcBase + s * 3 + 2];
            }
        }
        int excl = blockScanExcl(cnt, wsum, tid);
        if (tid == 0) cntT = wsum[31];
        for (int q = 0; q < 4; q++) {
            if (f[q] && excl < 2048) {
                ctx[excl] = rx[q]; cty[excl] = ry[q]; ctz[excl] = rz[q];
                tpos[excl] = (unsigned short)(tid * 4 + q);
                excl++;
            } else if (f[q]) excl++;
        }
    }
    for (int i = tid; i < NBX * NBX * NBZ; i += NTH) binCnt[i] = 0;
    if (tid < 64) taken[tid] = 0u;
    for (int q = 0; q < 4; q++) { tpF[tid * 4 + q] = 0; mtF[tid * 4 + q] = 0; }
    __syncthreads();

    const int KP = min(cntP, 2048), KT = min(cntT, 2048);

    // ---- bin kept targets ----
    for (int ci = tid; ci < KT; ci += NTH) {
        int bx, by, bz;
        binCoords(ctx[ci], cty[ci], ctz[ci], invXY, invZ, bx, by, bz);
        atomicAdd(&binCnt[(bz * NBX + by) * NBX + bx], 1u);
    }
    __syncthreads();
    {
        int base8 = tid * 8;
        int loc[8]; int s = 0;
        for (int k2 = 0; k2 < 8; k2++) { loc[k2] = s; s += (int)binCnt[base8 + k2]; }
        int ex = blockScanExcl(s, wsum, tid);
        for (int k2 = 0; k2 < 8; k2++) binStart[base8 + k2] = (unsigned)(ex + loc[k2]);
    }
    __syncthreads();
    for (int i = tid; i < NBX * NBX * NBZ; i += NTH) binCnt[i] = 0;
    __syncthreads();
    for (int ci = tid; ci < KT; ci += NTH) {
        int bx, by, bz;
        binCoords(ctx[ci], cty[ci], ctz[ci], invXY, invZ, bx, by, bz);
        int bb = (bz * NBX + by) * NBX + bx;
        unsigned off = atomicAdd(&binCnt[bb], 1u);
        binPts[binStart[bb] + off] = (unsigned short)ci;
    }
    __syncthreads();

    // ---- build per-pred sorted candidate lists (cap CAP) ----
    for (int ci = tid; ci < KP; ci += NTH) {
        float px = cpx[ci], py = cpy[ci], pz = cpz[ci];
        int bx, by, bz;
        binCoords(px, py, pz, invXY, invZ, bx, by, bz);
        unsigned short* cl = cand + ci * CAP;
        int nc = 0;
        for (int nb = 0; nb < 27; nb++) {
            int dxb = nb % 3 - 1, dyb = (nb / 3) % 3 - 1, dzb = nb / 9 - 1;
            int X = bx + dxb, Y = by + dyb, Z = bz + dzb;
            if (X < 0 || X >= NBX || Y < 0 || Y >= NBX || Z < 0 || Z >= NBZ) continue;
            int bb = (Z * NBX + Y) * NBX + X;
            unsigned st = binStart[bb], cn = binCnt[bb];
            for (unsigned p = 0; p < cn; p++) {
                int a = binPts[st + p];
                float d2 = dist2(px, py, pz, ctx[a], cty[a], ctz[a]);
                if (d2 < dd) {
                    if (nc < CAP) {
                        int k2 = nc;
                        while (k2 > 0 && cl[k2 - 1] > a) { cl[k2] = cl[k2 - 1]; k2--; }
                        cl[k2] = (unsigned short)a;
                        nc++;
                    } else if (a < cl[CAP - 1]) {
                        int k2 = CAP - 1;
                        while (k2 > 0 && cl[k2 - 1] > a) { cl[k2] = cl[k2 - 1]; k2--; }
                        cl[k2] = (unsigned short)a;
                    }
                }
            }
        }
        candCnt[ci] = (unsigned char)nc;
    }
    __syncthreads();

    // ---- sequential greedy resolution (tid 0) ----
    if (tid == 0) {
        for (int i = 0; i < KP; i++) {
            int nc = candCnt[i];
            const unsigned short* cl = cand + i * CAP;
            for (int k2 = 0; k2 < nc; k2++) {
                int j = cl[k2];
                unsigned w = taken[j >> 5];
                if (!((w >> (j & 31)) & 1u)) {
                    taken[j >> 5] = w | (1u << (j & 31));
                    tpF[ppos[i]] = 1;
                    mtF[tpos[j]] = 1;
                    break;
                }
            }
        }
    }
    __syncthreads();

    // ---- write tp/fp/fn ----
    const int tpB = OFF_TP + (b * 2 + e) * 4096;
    const int fpB = OFF_FP + (b * 2 + e) * 4096;
    const int fnB = OFF_FN + (b * 2 + e) * 4096;
    for (int q = 0; q < 4; q++) {
        int s = tid * 4 + q;
        int tp = tpF[s];
        int kp = (out[kpBase + s] > 0.5f) ? 1 : 0;
        int kt = (out[ktBase + s] > 0.5f) ? 1 : 0;
        out[tpB + s] = (float)tp;
        out[fpB + s] = (kp && !tp) ? 1.0f : 0.0f;
        out[fnB + s] = (kt && !mtF[s]) ? 1.0f : 0.0f;
    }
}

// ---------------------------------------------------------------------------
extern "C" void kernel_launch(void* const* d_in, const int* in_sizes, int n_in,
                              void* d_out, int out_size)
{
    const float* pred = (const float*)d_in[0];
    const float* targ = (const float*)d_in[1];
    float* out = (float*)d_out;

    cudaFuncSetAttribute(k_sort_nms, cudaFuncAttributeMaxDynamicSharedMemorySize, 139 * 1024);
    cudaFuncSetAttribute(k_match, cudaFuncAttributeMaxDynamicSharedMemorySize, 184 * 1024);

    k_sort_nms<<<16, NTH, 139 * 1024>>>(pred, targ, out);
    k_match<<<8, NTH, 184 * 1024>>>(out);
}

// round 3
// speedup vs baseline: 2.9200x; 1.3059x over previous
#include <cuda_runtime.h>
#include <cstdint>

#define NPTS 4096
#define NTH  1024

// d_out float32 layout:
//   Pc [4][2][4096][3] @0, Tc @98304, keepP @196608, keepT @229376,
//   tp @262144, fp @294912, fn @327680
#define OFF_TC 98304
#define OFF_KP 196608
#define OFF_KT 229376
#define OFF_TP 262144
#define OFF_FP 294912
#define OFF_FN 327680

#define NBX 32
#define NBZ 8

__device__ __forceinline__ float dist2(float ax, float ay, float az,
                                       float bx, float by, float bz) {
    float dx = __fadd_rn(ax, -bx);
    float dy = __fadd_rn(ay, -by);
    float dz = __fadd_rn(az, -bz);
    return __fadd_rn(__fadd_rn(__fmul_rn(dx, dx), __fmul_rn(dy, dy)),
                     __fmul_rn(dz, dz));
}

__device__ __forceinline__ int clampi(int v, int lo, int hi) {
    return v < lo ? lo : (v > hi ? hi : v);
}

__device__ __forceinline__ void binCoords(float x, float y, float z,
                                          float invXY, float invZ,
                                          int& bx, int& by, int& bz) {
    bx = clampi((int)floorf(__fmul_rn(__fadd_rn(x, 4.5f), invXY)), 0, NBX - 1);
    by = clampi((int)floorf(__fmul_rn(__fadd_rn(y, 4.5f), invXY)), 0, NBX - 1);
    bz = clampi((int)floorf(__fmul_rn(__fadd_rn(z, 4.0f), invZ)),  0, NBZ - 1);
}

__device__ __forceinline__ int blockScanExcl(int cnt, int* wsum, int tid) {
    int lane = tid & 31, wid = tid >> 5;
    int v = cnt;
    for (int o = 1; o < 32; o <<= 1) {
        int nn = __shfl_up_sync(0xFFFFFFFFu, v, o);
        if (lane >= o) v += nn;
    }
    if (lane == 31) wsum[wid] = v;
    __syncthreads();
    if (wid == 0) {
        int w = wsum[lane];
        for (int o = 1; o < 32; o <<= 1) {
            int nn = __shfl_up_sync(0xFFFFFFFFu, w, o);
            if (lane >= o) w += nn;
        }
        wsum[lane] = w;
    }
    __syncthreads();
    return v - cnt + (wid ? wsum[wid - 1] : 0);
}

// ---------------------------------------------------------------------------
// Kernel 1: per (tensor, b, e): transform -> hybrid bitonic sort -> binned NMS
// ---------------------------------------------------------------------------
__global__ void __launch_bounds__(1024) k_sort_nms(const float* __restrict__ pred,
                                                   const float* __restrict__ targ,
                                                   float* __restrict__ out)
{
    extern __shared__ unsigned char sm[];
    unsigned long long* key = (unsigned long long*)sm;          // 32KB
    float* cx = (float*)sm;                                     // alias after sort readback
    float* cy = cx + 4096;
    float* cz = (float*)(sm + 32 * 1024);
    unsigned short* spos = (unsigned short*)(sm + 48 * 1024);
    unsigned char* keepc = (unsigned char*)(sm + 56 * 1024);
    unsigned char* fullk = (unsigned char*)(sm + 60 * 1024);
    unsigned long long* mat = (unsigned long long*)(sm + 64 * 1024);
    unsigned int* binCnt = (unsigned int*)(sm + 66 * 1024);
    unsigned int* binStart = (unsigned int*)(sm + 98 * 1024);
    unsigned short* binPts = (unsigned short*)(sm + 130 * 1024);

    __shared__ int wsum[32];
    __shared__ unsigned long long supp;

    const int tid = threadIdx.x;
    const int bi = blockIdx.x;
    const int t = bi >> 3;
    const int be = bi & 7;
    const int b = be >> 1;
    const int e = be & 1;
    const float* in = (t == 0) ? pred : targ;
    const float de = (e == 0) ? (float)(0.74 * 1.4) : (float)(0.528 * 1.4);
    const float dd = __fmul_rn(de, de);
    const float cellXY = fmaxf(de, 1.02f);
    const float invXY = 1.0f / cellXY;
    const float invZ = 1.0f / 1.3125f;

    // ---- build keys directly into registers, slot layout: elem q*1024+tid ----
    unsigned long long v[4];
    for (int q = 0; q < 4; q++) {
        int n = q * 1024 + tid;
        int z = n >> 10, x = (n >> 5) & 31, y = n & 31;
        int base = ((((b * 32 + x) * 32 + y) * 4 + z) * 8) + e * 4;
        float conf = in[base + 3];
        unsigned u = __float_as_uint(conf);
        u = (u & 0x80000000u) ? ~u : (u | 0x80000000u);
        v[q] = (((unsigned long long)(~u)) << 32) | (unsigned)n;
    }

    // ---- hybrid bitonic sort (ascending) ----
    for (int k = 2; k <= NPTS; k <<= 1) {
        for (int j = k >> 1; j > 0; j >>= 1) {
            if (j >= 1024) {
                int js = j >> 10;
                #pragma unroll
                for (int qa = 0; qa < 4; qa++) {
                    int qb = qa ^ js;
                    if (qb > qa) {
                        int i = qa * 1024 + tid;
                        bool up = ((i & k) == 0);
                        if ((v[qa] > v[qb]) == up) {
                            unsigned long long tmp = v[qa]; v[qa] = v[qb]; v[qb] = tmp;
                        }
                    }
                }
            } else if (j >= 32) {
                #pragma unroll
                for (int q = 0; q < 4; q++) key[q * 1024 + tid] = v[q];
                __syncthreads();
                #pragma unroll
                for (int q = 0; q < 4; q++) {
                    unsigned long long p = key[q * 1024 + (tid ^ j)];
                    int i = q * 1024 + tid;
                    bool up = ((i & k) == 0);
                    bool lower = ((tid & j) == 0);
                    bool kmin = (lower == up);
                    unsigned long long mn = v[q] < p ? v[q] : p;
                    unsigned long long mx = v[q] < p ? p : v[q];
                    v[q] = kmin ? mn : mx;
                }
                __syncthreads();
            } else {
                #pragma unroll
                for (int q = 0; q < 4; q++) {
                    unsigned long long p = __shfl_xor_sync(0xFFFFFFFFu, v[q], j);
                    int i = q * 1024 + tid;
                    bool up = ((i & k) == 0);
                    bool lower = ((tid & j) == 0);
                    bool kmin = (lower == up);
                    unsigned long long mn = v[q] < p ? v[q] : p;
                    unsigned long long mx = v[q] < p ? p : v[q];
                    v[q] = kmin ? mn : mx;
                }
            }
        }
    }

    // dump sorted keys to smem, re-read in thread-contiguous order
    #pragma unroll
    for (int q = 0; q < 4; q++) key[q * 1024 + tid] = v[q];
    __syncthreads();
    unsigned long long myk[4];
    for (int q = 0; q < 4; q++) myk[q] = key[tid * 4 + q];

    // ---- coords + write Pc/Tc + compact valid ----
    float rx[4], ry[4], rz[4];
    int vflag[4]; int cnt = 0;
    for (int q = 0; q < 4; q++) {
        int n = (int)(myk[q] & 0xFFFFFFFFull);
        int z = n >> 10, x = (n >> 5) & 31, y = n & 31;
        int base = ((((b * 32 + x) * 32 + y) * 4 + z) * 8) + e * 4;
        float4 vv = *(const float4*)(in + base);
        float c0 = __fmul_rn(__fadd_rn(vv.z, (float)z), 0.75f);
        float c1 = __fmul_rn(__fadd_rn(vv.x, (float)x), 0.78125f);
        float c2 = __fmul_rn(__fadd_rn(vv.y, (float)y), 0.78125f);
        rx[q] = c0; ry[q] = c1; rz[q] = c2;
        vflag[q] = (vv.w > 0.5f) ? 1 : 0;
        cnt += vflag[q];
        int s = tid * 4 + q;
        int ob = (t ? OFF_TC : 0) + ((b * 2 + e) * 4096 + s) * 3;
        out[ob + 0] = c0; out[ob + 1] = c1; out[ob + 2] = c2;
    }
    __syncthreads();   // key reads done before aliased cx/cy writes

    int excl = blockScanExcl(cnt, wsum, tid);
    int m = wsum[31];

    for (int q = 0; q < 4; q++) {
        if (vflag[q]) {
            cx[excl] = rx[q]; cy[excl] = ry[q]; cz[excl] = rz[q];
            spos[excl] = (unsigned short)(tid * 4 + q);
            excl++;
        }
    }
    for (int i = tid; i < NBX * NBX * NBZ; i += NTH) binCnt[i] = 0;
    __syncthreads();

    // ---- build bins ----
    for (int ci = tid; ci < m; ci += NTH) {
        int bx, by, bz;
        binCoords(cx[ci], cy[ci], cz[ci], invXY, invZ, bx, by, bz);
        atomicAdd(&binCnt[(bz * NBX + by) * NBX + bx], 1u);
    }
    __syncthreads();
    {
        int base8 = tid * 8;
        int loc[8]; int s = 0;
        for (int k2 = 0; k2 < 8; k2++) { loc[k2] = s; s += (int)binCnt[base8 + k2]; }
        int ex = blockScanExcl(s, wsum, tid);
        for (int k2 = 0; k2 < 8; k2++) binStart[base8 + k2] = (unsigned)(ex + loc[k2]);
    }
    __syncthreads();
    for (int i = tid; i < NBX * NBX * NBZ; i += NTH) binCnt[i] = 0;
    __syncthreads();
    for (int ci = tid; ci < m; ci += NTH) {
        int bx, by, bz;
        binCoords(cx[ci], cy[ci], cz[ci], invXY, invZ, bx, by, bz);
        int bb = (bz * NBX + by) * NBX + bx;
        unsigned off = atomicAdd(&binCnt[bb], 1u);
        binPts[binStart[bb] + off] = (unsigned short)ci;
    }
    __syncthreads();

    // ---- chunked greedy NMS ----
    int nchunks = (m + 63) >> 6;
    for (int c = 0; c < nchunks; c++) {
        int cb = c * 64;
        int cc = min(64, m - cb);
        if (tid == 0) supp = 0ull;
        if (tid < 64) mat[tid] = 0ull;
        __syncthreads();

        int jj = tid >> 4, sub = tid & 15;
        if (jj < cc) {
            int j = cb + jj;
            float px = cx[j], py = cy[j], pz = cz[j];
            int bx, by, bz;
            binCoords(px, py, pz, invXY, invZ, bx, by, bz);
            bool suppressed = false;
            for (int nb = sub; nb < 27; nb += 16) {
                int dxb = nb % 3 - 1, dyb = (nb / 3) % 3 - 1, dzb = nb / 9 - 1;
                int X = bx + dxb, Y = by + dyb, Z = bz + dzb;
                if (X < 0 || X >= NBX || Y < 0 || Y >= NBX || Z < 0 || Z >= NBZ) continue;
                int bb = (Z * NBX + Y) * NBX + X;
                unsigned st = binStart[bb], cn = binCnt[bb];
                for (unsigned p = 0; p < cn; p++) {
                    int a = binPts[st + p];
                    if (a >= j) continue;
                    float d2 = dist2(px, py, pz, cx[a], cy[a], cz[a]);
                    if (d2 < dd) {
                        if (a < cb) { if (keepc[a]) suppressed = true; }
                        else atomicOr(&mat[a - cb], 1ull << jj);
                    }
                }
            }
            if (suppressed) atomicOr(&supp, 1ull << jj);
        }
        __syncthreads();

        if (tid == 0) {
            unsigned long long s = supp;
            #pragma unroll
            for (int q = 0; q < 64; q++) {
                unsigned long long mj = mat[q];
                bool kp = !((s >> q) & 1ull);
                if (kp) s |= mj;
                if (q < cc) keepc[cb + q] = kp ? 1 : 0;
            }
        }
        __syncthreads();
    }

    // ---- scatter keep, write mask ----
    for (int q = 0; q < 4; q++) fullk[tid * 4 + q] = 0;
    __syncthreads();
    for (int ci = tid; ci < m; ci += NTH) fullk[spos[ci]] = keepc[ci];
    __syncthreads();
    int kb = (t ? OFF_KT : OFF_KP) + (b * 2 + e) * 4096;
    for (int q = 0; q < 4; q++) {
        int s = tid * 4 + q;
        out[kb + s] = (float)fullk[s];
    }
}

// ---------------------------------------------------------------------------
// Kernel 2: per (b,e) greedy matching: binned candidates + wave resolution
// smem:
//  0 cpx 8K ; 8K cpy ; 16K cpz ; 24K ctx ; 32K cty ; 40K ctz
//  48K ppos ; 52K tpos
//  56K binCnt 32K (later aliased: minIdx u32[2048] = 8K)
//  88K binStart 32K (later aliased: finP u8[2048])
//  120K binPts 4K
//  124K candCnt 2K ; 126K cand u16[2048*12] 48K
//  174K tpF 4K ; 178K mtF 4K ; 182K taken u32[64]
// ---------------------------------------------------------------------------
#define CAP 12
__global__ void __launch_bounds__(1024) k_match(float* __restrict__ out)
{
    extern __shared__ unsigned char sm[];
    float* cpx = (float*)sm;
    float* cpy = (float*)(sm + 8 * 1024);
    float* cpz = (float*)(sm + 16 * 1024);
    float* ctx = (float*)(sm + 24 * 1024);
    float* cty = (float*)(sm + 32 * 1024);
    float* ctz = (float*)(sm + 40 * 1024);
    unsigned short* ppos = (unsigned short*)(sm + 48 * 1024);
    unsigned short* tpos = (unsigned short*)(sm + 52 * 1024);
    unsigned int* binCnt = (unsigned int*)(sm + 56 * 1024);
    unsigned int* binStart = (unsigned int*)(sm + 88 * 1024);
    unsigned short* binPts = (unsigned short*)(sm + 120 * 1024);
    unsigned char* candCnt = (unsigned char*)(sm + 124 * 1024);
    unsigned short* cand = (unsigned short*)(sm + 126 * 1024);
    unsigned char* tpF = (unsigned char*)(sm + 174 * 1024);
    unsigned char* mtF = (unsigned char*)(sm + 178 * 1024);
    unsigned int* taken = (unsigned int*)(sm + 182 * 1024);
    // wave-resolution aliases (bins dead by then)
    unsigned int* minIdx = (unsigned int*)(sm + 56 * 1024);   // [2048]
    unsigned char* finP = (unsigned char*)(sm + 88 * 1024);   // [2048]

    __shared__ int wsum[32];
    __shared__ int cntP, cntT;
    __shared__ int remaining;

    const int tid = threadIdx.x;
    const int be = blockIdx.x;
    const int b = be >> 1, e = be & 1;
    const float de = (e == 0) ? (float)(0.74 * 1.4) : (float)(0.528 * 1.4);
    const float dd = __fmul_rn(de, de);
    const float cellXY = fmaxf(de, 1.02f);
    const float invXY = 1.0f / cellXY;
    const float invZ = 1.0f / 1.3125f;

    const int pcBase = (b * 2 + e) * 4096 * 3;
    const int tcBase = OFF_TC + pcBase;
    const int kpBase = OFF_KP + (b * 2 + e) * 4096;
    const int ktBase = OFF_KT + (b * 2 + e) * 4096;

    // ---- compact kept preds ----
    {
        float rx[4], ry[4], rz[4]; int f[4]; int cnt = 0;
        for (int q = 0; q < 4; q++) {
            int s = tid * 4 + q;
            int kp = (out[kpBase + s] > 0.5f) ? 1 : 0;
            f[q] = kp; cnt += kp;
            if (kp) {
                rx[q] = out[pcBase + s * 3 + 0];
                ry[q] = out[pcBase + s * 3 + 1];
                rz[q] = out[pcBase + s * 3 + 2];
            }
        }
        int excl = blockScanExcl(cnt, wsum, tid);
        if (tid == 0) cntP = wsum[31];
        for (int q = 0; q < 4; q++) {
            if (f[q] && excl < 2048) {
                cpx[excl] = rx[q]; cpy[excl] = ry[q]; cpz[excl] = rz[q];
                ppos[excl] = (unsigned short)(tid * 4 + q);
                excl++;
            } else if (f[q]) excl++;
        }
        __syncthreads();
    }
    // ---- compact kept targets ----
    {
        float rx[4], ry[4], rz[4]; int f[4]; int cnt = 0;
        for (int q = 0; q < 4; q++) {
            int s = tid * 4 + q;
            int kt = (out[ktBase + s] > 0.5f) ? 1 : 0;
            f[q] = kt; cnt += kt;
            if (kt) {
                rx[q] = out[tcBase + s * 3 + 0];
                ry[q] = out[tcBase + s * 3 + 1];
                rz[q] = out[tcBase + s * 3 + 2];
            }
        }
        int excl = blockScanExcl(cnt, wsum, tid);
        if (tid == 0) cntT = wsum[31];
        for (int q = 0; q < 4; q++) {
            if (f[q] && excl < 2048) {
                ctx[excl] = rx[q]; cty[excl] = ry[q]; ctz[excl] = rz[q];
                tpos[excl] = (unsigned short)(tid * 4 + q);
                excl++;
            } else if (f[q]) excl++;
        }
    }
    for (int i = tid; i < NBX * NBX * NBZ; i += NTH) binCnt[i] = 0;
    if (tid < 64) taken[tid] = 0u;
    for (int q = 0; q < 4; q++) { tpF[tid * 4 + q] = 0; mtF[tid * 4 + q] = 0; }
    __syncthreads();

    const int KP = min(cntP, 2048), KT = min(cntT, 2048);

    // ---- bin kept targets ----
    for (int ci = tid; ci < KT; ci += NTH) {
        int bx, by, bz;
        binCoords(ctx[ci], cty[ci], ctz[ci], invXY, invZ, bx, by, bz);
        atomicAdd(&binCnt[(bz * NBX + by) * NBX + bx], 1u);
    }
    __syncthreads();
    {
        int base8 = tid * 8;
        int loc[8]; int s = 0;
        for (int k2 = 0; k2 < 8; k2++) { loc[k2] = s; s += (int)binCnt[base8 + k2]; }
        int ex = blockScanExcl(s, wsum, tid);
        for (int k2 = 0; k2 < 8; k2++) binStart[base8 + k2] = (unsigned)(ex + loc[k2]);
    }
    __syncthreads();
    for (int i = tid; i < NBX * NBX * NBZ; i += NTH) binCnt[i] = 0;
    __syncthreads();
    for (int ci = tid; ci < KT; ci += NTH) {
        int bx, by, bz;
        binCoords(ctx[ci], cty[ci], ctz[ci], invXY, invZ, bx, by, bz);
        int bb = (bz * NBX + by) * NBX + bx;
        unsigned off = atomicAdd(&binCnt[bb], 1u);
        binPts[binStart[bb] + off] = (unsigned short)ci;
    }
    __syncthreads();

    // ---- build per-pred sorted candidate lists ----
    for (int ci = tid; ci < KP; ci += NTH) {
        float px = cpx[ci], py = cpy[ci], pz = cpz[ci];
        int bx, by, bz;
        binCoords(px, py, pz, invXY, invZ, bx, by, bz);
        unsigned short* cl = cand + ci * CAP;
        int nc = 0;
        for (int nb = 0; nb < 27; nb++) {
            int dxb = nb % 3 - 1, dyb = (nb / 3) % 3 - 1, dzb = nb / 9 - 1;
            int X = bx + dxb, Y = by + dyb, Z = bz + dzb;
            if (X < 0 || X >= NBX || Y < 0 || Y >= NBX || Z < 0 || Z >= NBZ) continue;
            int bb = (Z * NBX + Y) * NBX + X;
            unsigned st = binStart[bb], cn = binCnt[bb];
            for (unsigned p = 0; p < cn; p++) {
                int a = binPts[st + p];
                float d2 = dist2(px, py, pz, ctx[a], cty[a], ctz[a]);
                if (d2 < dd) {
                    if (nc < CAP) {
                        int k2 = nc;
                        while (k2 > 0 && cl[k2 - 1] > a) { cl[k2] = cl[k2 - 1]; k2--; }
                        cl[k2] = (unsigned short)a;
                        nc++;
                    } else if (a < cl[CAP - 1]) {
                        int k2 = CAP - 1;
                        while (k2 > 0 && cl[k2 - 1] > a) { cl[k2] = cl[k2 - 1]; k2--; }
                        cl[k2] = (unsigned short)a;
                    }
                }
            }
        }
        candCnt[ci] = (unsigned char)nc;
    }
    // bins dead from here; init wave state (finP aliases binStart)
    if (tid == 0) remaining = KP;
    __syncthreads();
    for (int i = tid; i < KP; i += NTH) finP[i] = 0;
    __syncthreads();

    // ---- wave-parallel greedy resolution (exact sequential semantics) ----
    while (true) {
        if (remaining <= 0) break;              // uniform read post-barrier
        for (int t2 = tid; t2 < KT; t2 += NTH) minIdx[t2] = 0x7FFFFFFFu;
        __syncthreads();
        for (int i = tid; i < KP; i += NTH) {
            if (!finP[i]) {
                int nc = candCnt[i];
                const unsigned short* cl = cand + i * CAP;
                for (int k2 = 0; k2 < nc; k2++)
                    atomicMin(&minIdx[cl[k2]], (unsigned)i);
            }
        }
        __syncthreads();
        for (int i = tid; i < KP; i += NTH) {
            if (!finP[i]) {
                int nc = candCnt[i];
                const unsigned short* cl = cand + i * CAP;
                bool ok = true;
                for (int k2 = 0; k2 < nc; k2++)
                    if (minIdx[cl[k2]] < (unsigned)i) { ok = false; break; }
                if (ok) {
                    for (int k2 = 0; k2 < nc; k2++) {
                        int j = cl[k2];
                        if (!((taken[j >> 5] >> (j & 31)) & 1u)) {
                            atomicOr(&taken[j >> 5], 1u << (j & 31));
                            tpF[ppos[i]] = 1;
                            mtF[tpos[j]] = 1;
                            break;
                        }
                    }
                    finP[i] = 1;
                    atomicSub(&remaining, 1);
                }
            }
        }
        __syncthreads();
    }

    // ---- write tp/fp/fn ----
    const int tpB = OFF_TP + (b * 2 + e) * 4096;
    const int fpB = OFF_FP + (b * 2 + e) * 4096;
    const int fnB = OFF_FN + (b * 2 + e) * 4096;
    for (int q = 0; q < 4; q++) {
        int s = tid * 4 + q;
        int tp = tpF[s];
        int kp = (out[kpBase + s] > 0.5f) ? 1 : 0;
        int kt = (out[ktBase + s] > 0.5f) ? 1 : 0;
        out[tpB + s] = (float)tp;
        out[fpB + s] = (kp && !tp) ? 1.0f : 0.0f;
        out[fnB + s] = (kt && !mtF[s]) ? 1.0f : 0.0f;
    }
}

// ---------------------------------------------------------------------------
extern "C" void kernel_launch(void* const* d_in, const int* in_sizes, int n_in,
                              void* d_out, int out_size)
{
    const float* pred = (const float*)d_in[0];
    const float* targ = (const float*)d_in[1];
    float* out = (float*)d_out;

    cudaFuncSetAttribute(k_sort_nms, cudaFuncAttributeMaxDynamicSharedMemorySize, 139 * 1024);
    cudaFuncSetAttribute(k_match, cudaFuncAttributeMaxDynamicSharedMemorySize, 184 * 1024);

    k_sort_nms<<<16, NTH, 139 * 1024>>>(pred, targ, out);
    k_match<<<8, NTH, 184 * 1024>>>(out);
}

// round 4
// speedup vs baseline: 2.9798x; 1.0205x over previous
#include <cuda_runtime.h>
#include <cstdint>

#define NPTS 4096
#define NTH  1024

// d_out float32 layout:
//   Pc [4][2][4096][3] @0, Tc @98304, keepP @196608, keepT @229376,
//   tp @262144, fp @294912, fn @327680
#define OFF_TC 98304
#define OFF_KP 196608
#define OFF_KT 229376
#define OFF_TP 262144
#define OFF_FP 294912
#define OFF_FN 327680

#define NBX 32
#define NBZ 8
#define CAP 12

__device__ unsigned g_sense = 0;
__device__ unsigned g_count = 0;

__device__ __forceinline__ float dist2(float ax, float ay, float az,
                                       float bx, float by, float bz) {
    float dx = __fadd_rn(ax, -bx);
    float dy = __fadd_rn(ay, -by);
    float dz = __fadd_rn(az, -bz);
    return __fadd_rn(__fadd_rn(__fmul_rn(dx, dx), __fmul_rn(dy, dy)),
                     __fmul_rn(dz, dz));
}

__device__ __forceinline__ int clampi(int v, int lo, int hi) {
    return v < lo ? lo : (v > hi ? hi : v);
}

__device__ __forceinline__ void binCoords(float x, float y, float z,
                                          float invXY, float invZ,
                                          int& bx, int& by, int& bz) {
    bx = clampi((int)floorf(__fmul_rn(__fadd_rn(x, 4.5f), invXY)), 0, NBX - 1);
    by = clampi((int)floorf(__fmul_rn(__fadd_rn(y, 4.5f), invXY)), 0, NBX - 1);
    bz = clampi((int)floorf(__fmul_rn(__fadd_rn(z, 4.0f), invZ)),  0, NBZ - 1);
}

__device__ __forceinline__ int blockScanExcl(int cnt, int* wsum, int tid) {
    int lane = tid & 31, wid = tid >> 5;
    int v = cnt;
    for (int o = 1; o < 32; o <<= 1) {
        int nn = __shfl_up_sync(0xFFFFFFFFu, v, o);
        if (lane >= o) v += nn;
    }
    if (lane == 31) wsum[wid] = v;
    __syncthreads();
    if (wid == 0) {
        int w = wsum[lane];
        for (int o = 1; o < 32; o <<= 1) {
            int nn = __shfl_up_sync(0xFFFFFFFFu, w, o);
            if (lane >= o) w += nn;
        }
        wsum[lane] = w;
    }
    __syncthreads();
    return v - cnt + (wid ? wsum[wid - 1] : 0);
}

// ---------------------------------------------------------------------------
// Fused persistent kernel: 16 blocks.
// Phase 1 (all 16): transform -> hybrid bitonic sort -> binned NMS -> out
// grid barrier
// Phase 2 (blocks 0-7): binned greedy matching -> tp/fp/fn
// ---------------------------------------------------------------------------
__global__ void __launch_bounds__(1024, 1) k_fused(const float* __restrict__ pred,
                                                   const float* __restrict__ targ,
                                                   float* __restrict__ out)
{
    extern __shared__ unsigned char sm[];
    __shared__ int wsum[32];

    const int tid = threadIdx.x;
    const int bi = blockIdx.x;

    // ======================= PHASE 1: sort + NMS ===========================
    {
        unsigned long long* key = (unsigned long long*)sm;          // 32KB
        float* cx = (float*)sm;                                     // alias post-sort
        float* cy = cx + 4096;
        float* cz = (float*)(sm + 32 * 1024);
        unsigned short* spos = (unsigned short*)(sm + 48 * 1024);
        unsigned char* keepc = (unsigned char*)(sm + 56 * 1024);
        unsigned char* fullk = (unsigned char*)(sm + 60 * 1024);
        unsigned long long* mat = (unsigned long long*)(sm + 64 * 1024);
        unsigned int* binCnt = (unsigned int*)(sm + 66 * 1024);
        unsigned int* binStart = (unsigned int*)(sm + 98 * 1024);
        unsigned short* binPts = (unsigned short*)(sm + 130 * 1024);

        __shared__ unsigned long long supp;

        const int t = bi >> 3;
        const int be = bi & 7;
        const int b = be >> 1;
        const int e = be & 1;
        const float* in = (t == 0) ? pred : targ;
        const float de = (e == 0) ? (float)(0.74 * 1.4) : (float)(0.528 * 1.4);
        const float dd = __fmul_rn(de, de);
        const float cellXY = fmaxf(de, 1.02f);
        const float invXY = 1.0f / cellXY;
        const float invZ = 1.0f / 1.3125f;

        // ---- coalesced conf gather: p linear over (x,y,z), scatter to key[n] ----
        for (int q = 0; q < 4; q++) {
            int p = q * 1024 + tid;
            int x = p >> 7, y = (p >> 2) & 31, z = p & 3;
            int base = ((((b * 32 + x) * 32 + y) * 4 + z) * 8) + e * 4;
            float conf = in[base + 3];
            unsigned u = __float_as_uint(conf);
            u = (u & 0x80000000u) ? ~u : (u | 0x80000000u);
            int n = (z << 10) | (x << 5) | y;
            key[n] = (((unsigned long long)(~u)) << 32) | (unsigned)n;
        }
        __syncthreads();
        unsigned long long v[4];
        #pragma unroll
        for (int q = 0; q < 4; q++) v[q] = key[q * 1024 + tid];
        __syncthreads();

        // ---- hybrid bitonic sort (ascending) ----
        for (int k = 2; k <= NPTS; k <<= 1) {
            for (int j = k >> 1; j > 0; j >>= 1) {
                if (j >= 1024) {
                    int js = j >> 10;
                    #pragma unroll
                    for (int qa = 0; qa < 4; qa++) {
                        int qb = qa ^ js;
                        if (qb > qa) {
                            int i = qa * 1024 + tid;
                            bool up = ((i & k) == 0);
                            if ((v[qa] > v[qb]) == up) {
                                unsigned long long tmp = v[qa]; v[qa] = v[qb]; v[qb] = tmp;
                            }
                        }
                    }
                } else if (j >= 32) {
                    #pragma unroll
                    for (int q = 0; q < 4; q++) key[q * 1024 + tid] = v[q];
                    __syncthreads();
                    #pragma unroll
                    for (int q = 0; q < 4; q++) {
                        unsigned long long p = key[q * 1024 + (tid ^ j)];
                        int i = q * 1024 + tid;
                        bool up = ((i & k) == 0);
                        bool lower = ((tid & j) == 0);
                        bool kmin = (lower == up);
                        unsigned long long mn = v[q] < p ? v[q] : p;
                        unsigned long long mx = v[q] < p ? p : v[q];
                        v[q] = kmin ? mn : mx;
                    }
                    __syncthreads();
                } else {
                    #pragma unroll
                    for (int q = 0; q < 4; q++) {
                        unsigned long long p = __shfl_xor_sync(0xFFFFFFFFu, v[q], j);
                        int i = q * 1024 + tid;
                        bool up = ((i & k) == 0);
                        bool lower = ((tid & j) == 0);
                        bool kmin = (lower == up);
                        unsigned long long mn = v[q] < p ? v[q] : p;
                        unsigned long long mx = v[q] < p ? p : v[q];
                        v[q] = kmin ? mn : mx;
                    }
                }
            }
        }

        #pragma unroll
        for (int q = 0; q < 4; q++) key[q * 1024 + tid] = v[q];
        __syncthreads();
        unsigned long long myk[4];
        for (int q = 0; q < 4; q++) myk[q] = key[tid * 4 + q];

        // ---- coords + write Pc/Tc + compact valid ----
        float rx[4], ry[4], rz[4];
        int vflag[4]; int cnt = 0;
        for (int q = 0; q < 4; q++) {
            int n = (int)(myk[q] & 0xFFFFFFFFull);
            int z = n >> 10, x = (n >> 5) & 31, y = n & 31;
            int base = ((((b * 32 + x) * 32 + y) * 4 + z) * 8) + e * 4;
            float4 vv = *(const float4*)(in + base);
            float c0 = __fmul_rn(__fadd_rn(vv.z, (float)z), 0.75f);
            float c1 = __fmul_rn(__fadd_rn(vv.x, (float)x), 0.78125f);
            float c2 = __fmul_rn(__fadd_rn(vv.y, (float)y), 0.78125f);
            rx[q] = c0; ry[q] = c1; rz[q] = c2;
            vflag[q] = (vv.w > 0.5f) ? 1 : 0;
            cnt += vflag[q];
            int s = tid * 4 + q;
            int ob = (t ? OFF_TC : 0) + ((b * 2 + e) * 4096 + s) * 3;
            out[ob + 0] = c0; out[ob + 1] = c1; out[ob + 2] = c2;
        }
        __syncthreads();

        int excl = blockScanExcl(cnt, wsum, tid);
        int m = wsum[31];

        for (int q = 0; q < 4; q++) {
            if (vflag[q]) {
                cx[excl] = rx[q]; cy[excl] = ry[q]; cz[excl] = rz[q];
                spos[excl] = (unsigned short)(tid * 4 + q);
                excl++;
            }
        }
        for (int i = tid; i < NBX * NBX * NBZ; i += NTH) binCnt[i] = 0;
        __syncthreads();

        // ---- build bins ----
        for (int ci = tid; ci < m; ci += NTH) {
            int bx, by, bz;
            binCoords(cx[ci], cy[ci], cz[ci], invXY, invZ, bx, by, bz);
            atomicAdd(&binCnt[(bz * NBX + by) * NBX + bx], 1u);
        }
        __syncthreads();
        {
            int base8 = tid * 8;
            int loc[8]; int s = 0;
            for (int k2 = 0; k2 < 8; k2++) { loc[k2] = s; s += (int)binCnt[base8 + k2]; }
            int ex = blockScanExcl(s, wsum, tid);
            for (int k2 = 0; k2 < 8; k2++) binStart[base8 + k2] = (unsigned)(ex + loc[k2]);
        }
        __syncthreads();
        for (int i = tid; i < NBX * NBX * NBZ; i += NTH) binCnt[i] = 0;
        __syncthreads();
        for (int ci = tid; ci < m; ci += NTH) {
            int bx, by, bz;
            binCoords(cx[ci], cy[ci], cz[ci], invXY, invZ, bx, by, bz);
            int bb = (bz * NBX + by) * NBX + bx;
            unsigned off = atomicAdd(&binCnt[bb], 1u);
            binPts[binStart[bb] + off] = (unsigned short)ci;
        }
        __syncthreads();

        // ---- chunked greedy NMS ----
        int nchunks = (m + 63) >> 6;
        for (int c = 0; c < nchunks; c++) {
            int cb = c * 64;
            int cc = min(64, m - cb);
            if (tid == 0) supp = 0ull;
            if (tid < 64) mat[tid] = 0ull;
            __syncthreads();

            int jj = tid >> 4, sub = tid & 15;
            if (jj < cc) {
                int j = cb + jj;
                float px = cx[j], py = cy[j], pz = cz[j];
                int bx, by, bz;
                binCoords(px, py, pz, invXY, invZ, bx, by, bz);
                bool suppressed = false;
                for (int nb = sub; nb < 27; nb += 16) {
                    int dxb = nb % 3 - 1, dyb = (nb / 3) % 3 - 1, dzb = nb / 9 - 1;
                    int X = bx + dxb, Y = by + dyb, Z = bz + dzb;
                    if (X < 0 || X >= NBX || Y < 0 || Y >= NBX || Z < 0 || Z >= NBZ) continue;
                    int bb = (Z * NBX + Y) * NBX + X;
                    unsigned st = binStart[bb], cn = binCnt[bb];
                    for (unsigned p = 0; p < cn; p++) {
                        int a = binPts[st + p];
                        if (a >= j) continue;
                        float d2 = dist2(px, py, pz, cx[a], cy[a], cz[a]);
                        if (d2 < dd) {
                            if (a < cb) { if (keepc[a]) suppressed = true; }
                            else atomicOr(&mat[a - cb], 1ull << jj);
                        }
                    }
                }
                if (suppressed) atomicOr(&supp, 1ull << jj);
            }
            __syncthreads();

            if (tid == 0) {
                unsigned long long s = supp;
                #pragma unroll
                for (int q = 0; q < 64; q++) {
                    unsigned long long mj = mat[q];
                    bool kp = !((s >> q) & 1ull);
                    if (kp) s |= mj;
                    if (q < cc) keepc[cb + q] = kp ? 1 : 0;
                }
            }
            __syncthreads();
        }

        // ---- scatter keep, write mask ----
        for (int q = 0; q < 4; q++) fullk[tid * 4 + q] = 0;
        __syncthreads();
        for (int ci = tid; ci < m; ci += NTH) fullk[spos[ci]] = keepc[ci];
        __syncthreads();
        int kb = (t ? OFF_KT : OFF_KP) + (b * 2 + e) * 4096;
        for (int q = 0; q < 4; q++) {
            int s = tid * 4 + q;
            out[kb + s] = (float)fullk[s];
        }
    }

    // ======================= GRID BARRIER ==================================
    __threadfence();          // make this thread's out[] writes visible
    __syncthreads();
    if (tid == 0) {
        unsigned s0 = atomicAdd(&g_sense, 0u);
        unsigned c = atomicAdd(&g_count, 1u);
        if (c == (unsigned)(gridDim.x - 1)) {
            g_count = 0u;
            __threadfence();
            atomicAdd(&g_sense, 1u);
        } else {
            while (atomicAdd(&g_sense, 0u) == s0) __nanosleep(64);
        }
    }
    __syncthreads();
    if (bi >= 8) return;

    // ======================= PHASE 2: matching =============================
    {
        float* cpx = (float*)sm;
        float* cpy = (float*)(sm + 8 * 1024);
        float* cpz = (float*)(sm + 16 * 1024);
        float* ctx = (float*)(sm + 24 * 1024);
        float* cty = (float*)(sm + 32 * 1024);
        float* ctz = (float*)(sm + 40 * 1024);
        unsigned short* ppos = (unsigned short*)(sm + 48 * 1024);
        unsigned short* tpos = (unsigned short*)(sm + 52 * 1024);
        unsigned int* binCnt = (unsigned int*)(sm + 56 * 1024);
        unsigned int* binStart = (unsigned int*)(sm + 88 * 1024);
        unsigned short* binPts = (unsigned short*)(sm + 120 * 1024);
        unsigned char* candCnt = (unsigned char*)(sm + 124 * 1024);
        unsigned short* cand = (unsigned short*)(sm + 126 * 1024);
        unsigned char* tpF = (unsigned char*)(sm + 174 * 1024);
        unsigned char* mtF = (unsigned char*)(sm + 178 * 1024);
        unsigned int* taken = (unsigned int*)(sm + 182 * 1024);
        unsigned int* minIdx = (unsigned int*)(sm + 56 * 1024);   // alias binCnt
        unsigned char* finP = (unsigned char*)(sm + 88 * 1024);   // alias binStart

        __shared__ int cntP, cntT;
        __shared__ int remaining;

        const int be = bi;
        const int b = be >> 1, e = be & 1;
        const float de = (e == 0) ? (float)(0.74 * 1.4) : (float)(0.528 * 1.4);
        const float dd = __fmul_rn(de, de);
        const float cellXY = fmaxf(de, 1.02f);
        const float invXY = 1.0f / cellXY;
        const float invZ = 1.0f / 1.3125f;

        const int pcBase = (b * 2 + e) * 4096 * 3;
        const int tcBase = OFF_TC + pcBase;
        const int kpBase = OFF_KP + (b * 2 + e) * 4096;
        const int ktBase = OFF_KT + (b * 2 + e) * 4096;

        __syncthreads();   // smem reuse fence

        // ---- compact kept preds ----
        {
            float rx[4], ry[4], rz[4]; int f[4]; int cnt = 0;
            for (int q = 0; q < 4; q++) {
                int s = tid * 4 + q;
                int kp = (out[kpBase + s] > 0.5f) ? 1 : 0;
                f[q] = kp; cnt += kp;
                if (kp) {
                    rx[q] = out[pcBase + s * 3 + 0];
                    ry[q] = out[pcBase + s * 3 + 1];
                    rz[q] = out[pcBase + s * 3 + 2];
                }
            }
            int excl = blockScanExcl(cnt, wsum, tid);
            if (tid == 0) cntP = wsum[31];
            for (int q = 0; q < 4; q++) {
                if (f[q] && excl < 2048) {
                    cpx[excl] = rx[q]; cpy[excl] = ry[q]; cpz[excl] = rz[q];
                    ppos[excl] = (unsigned short)(tid * 4 + q);
                    excl++;
                } else if (f[q]) excl++;
            }
            __syncthreads();
        }
        // ---- compact kept targets ----
        {
            float rx[4], ry[4], rz[4]; int f[4]; int cnt = 0;
            for (int q = 0; q < 4; q++) {
                int s = tid * 4 + q;
                int kt = (out[ktBase + s] > 0.5f) ? 1 : 0;
                f[q] = kt; cnt += kt;
                if (kt) {
                    rx[q] = out[tcBase + s * 3 + 0];
                    ry[q] = out[tcBase + s * 3 + 1];
                    rz[q] = out[tcBase + s * 3 + 2];
                }
            }
            int excl = blockScanExcl(cnt, wsum, tid);
            if (tid == 0) cntT = wsum[31];
            for (int q = 0; q < 4; q++) {
                if (f[q] && excl < 2048) {
                    ctx[excl] = rx[q]; cty[excl] = ry[q]; ctz[excl] = rz[q];
                    tpos[excl] = (unsigned short)(tid * 4 + q);
                    excl++;
                } else if (f[q]) excl++;
            }
        }
        for (int i = tid; i < NBX * NBX * NBZ; i += NTH) binCnt[i] = 0;
        if (tid < 64) taken[tid] = 0u;
        if (tid == 0) remaining = 0;
        for (int q = 0; q < 4; q++) { tpF[tid * 4 + q] = 0; mtF[tid * 4 + q] = 0; }
        __syncthreads();

        const int KP = min(cntP, 2048), KT = min(cntT, 2048);

        // ---- bin kept targets ----
        for (int ci = tid; ci < KT; ci += NTH) {
            int bx, by, bz;
            binCoords(ctx[ci], cty[ci], ctz[ci], invXY, invZ, bx, by, bz);
            atomicAdd(&binCnt[(bz * NBX + by) * NBX + bx], 1u);
        }
        __syncthreads();
        {
            int base8 = tid * 8;
            int loc[8]; int s = 0;
            for (int k2 = 0; k2 < 8; k2++) { loc[k2] = s; s += (int)binCnt[base8 + k2]; }
            int ex = blockScanExcl(s, wsum, tid);
            for (int k2 = 0; k2 < 8; k2++) binStart[base8 + k2] = (unsigned)(ex + loc[k2]);
        }
        __syncthreads();
        for (int i = tid; i < NBX * NBX * NBZ; i += NTH) binCnt[i] = 0;
        __syncthreads();
        for (int ci = tid; ci < KT; ci += NTH) {
            int bx, by, bz;
            binCoords(ctx[ci], cty[ci], ctz[ci], invXY, invZ, bx, by, bz);
            int bb = (bz * NBX + by) * NBX + bx;
            unsigned off = atomicAdd(&binCnt[bb], 1u);
            binPts[binStart[bb] + off] = (unsigned short)ci;
        }
        __syncthreads();

        // ---- build per-pred sorted candidate lists ----
        for (int ci = tid; ci < KP; ci += NTH) {
            float px = cpx[ci], py = cpy[ci], pz = cpz[ci];
            int bx, by, bz;
            binCoords(px, py, pz, invXY, invZ, bx, by, bz);
            unsigned short* cl = cand + ci * CAP;
            int nc = 0;
            for (int nb = 0; nb < 27; nb++) {
                int dxb = nb % 3 - 1, dyb = (nb / 3) % 3 - 1, dzb = nb / 9 - 1;
                int X = bx + dxb, Y = by + dyb, Z = bz + dzb;
                if (X < 0 || X >= NBX || Y < 0 || Y >= NBX || Z < 0 || Z >= NBZ) continue;
                int bb = (Z * NBX + Y) * NBX + X;
                unsigned st = binStart[bb], cn = binCnt[bb];
                for (unsigned p = 0; p < cn; p++) {
                    int a = binPts[st + p];
                    float d2 = dist2(px, py, pz, ctx[a], cty[a], ctz[a]);
                    if (d2 < dd) {
                        if (nc < CAP) {
                            int k2 = nc;
                            while (k2 > 0 && cl[k2 - 1] > a) { cl[k2] = cl[k2 - 1]; k2--; }
                            cl[k2] = (unsigned short)a;
                            nc++;
                        } else if (a < cl[CAP - 1]) {
                            int k2 = CAP - 1;
                            while (k2 > 0 && cl[k2 - 1] > a) { cl[k2] = cl[k2 - 1]; k2--; }
                            cl[k2] = (unsigned short)a;
                        }
                    }
                }
            }
            candCnt[ci] = (unsigned char)nc;
        }
        __syncthreads();     // bins dead; finP aliases binStart

        // pre-finalize preds with no candidates
        {
            int act = 0;
            for (int i = tid; i < KP; i += NTH) {
                int a = (candCnt[i] > 0) ? 1 : 0;
                finP[i] = (unsigned char)(1 - a);
                act += a;
            }
            if (act) atomicAdd(&remaining, act);
        }
        __syncthreads();

        // ---- wave-parallel greedy resolution ----
        while (true) {
            if (remaining <= 0) break;
            for (int t2 = tid; t2 < KT; t2 += NTH) minIdx[t2] = 0x7FFFFFFFu;
            __syncthreads();
            for (int i = tid; i < KP; i += NTH) {
                if (!finP[i]) {
                    int nc = candCnt[i];
                    const unsigned short* cl = cand + i * CAP;
                    for (int k2 = 0; k2 < nc; k2++)
                        atomicMin(&minIdx[cl[k2]], (unsigned)i);
                }
            }
            __syncthreads();
            for (int i = tid; i < KP; i += NTH) {
                if (!finP[i]) {
                    int nc = candCnt[i];
                    const unsigned short* cl = cand + i * CAP;
                    bool ok = true;
                    for (int k2 = 0; k2 < nc; k2++)
                        if (minIdx[cl[k2]] < (unsigned)i) { ok = false; break; }
                    if (ok) {
                        for (int k2 = 0; k2 < nc; k2++) {
                            int j = cl[k2];
                            if (!((taken[j >> 5] >> (j & 31)) & 1u)) {
                                atomicOr(&taken[j >> 5], 1u << (j & 31));
                                tpF[ppos[i]] = 1;
                                mtF[tpos[j]] = 1;
                                break;
                            }
                        }
                        finP[i] = 1;
                        atomicSub(&remaining, 1);
                    }
                }
            }
            __syncthreads();
        }

        // ---- write tp/fp/fn ----
        const int tpB = OFF_TP + (b * 2 + e) * 4096;
        const int fpB = OFF_FP + (b * 2 + e) * 4096;
        const int fnB = OFF_FN + (b * 2 + e) * 4096;
        for (int q = 0; q < 4; q++) {
            int s = tid * 4 + q;
            int tp = tpF[s];
            int kp = (out[kpBase + s] > 0.5f) ? 1 : 0;
            int kt = (out[ktBase + s] > 0.5f) ? 1 : 0;
            out[tpB + s] = (float)tp;
            out[fpB + s] = (kp && !tp) ? 1.0f : 0.0f;
            out[fnB + s] = (kt && !mtF[s]) ? 1.0f : 0.0f;
        }
    }
}

// ---------------------------------------------------------------------------
extern "C" void kernel_launch(void* const* d_in, const int* in_sizes, int n_in,
                              void* d_out, int out_size)
{
    const float* pred = (const float*)d_in[0];
    const float* targ = (const float*)d_in[1];
    float* out = (float*)d_out;

    cudaFuncSetAttribute(k_fused, cudaFuncAttributeMaxDynamicSharedMemorySize, 185 * 1024);
    k_fused<<<16, NTH, 184 * 1024>>>(pred, targ, out);
}

// round 5
// speedup vs baseline: 3.3897x; 1.1376x over previous
#include <cuda_runtime.h>
#include <cstdint>

#define NPTS 4096
#define NTH  1024

// d_out float32 layout:
//   Pc [4][2][4096][3] @0, Tc @98304, keepP @196608, keepT @229376,
//   tp @262144, fp @294912, fn @327680
#define OFF_TC 98304
#define OFF_KP 196608
#define OFF_KT 229376
#define OFF_TP 262144
#define OFF_FP 294912
#define OFF_FN 327680

#define NBX 32
#define NBZ 8
#define CAP 12

__device__ unsigned g_sense = 0;
__device__ unsigned g_count = 0;
__device__ unsigned long long g_run0[16 * 4096];
__device__ unsigned long long g_run1[16 * 4096];

__device__ __forceinline__ float dist2(float ax, float ay, float az,
                                       float bx, float by, float bz) {
    float dx = __fadd_rn(ax, -bx);
    float dy = __fadd_rn(ay, -by);
    float dz = __fadd_rn(az, -bz);
    return __fadd_rn(__fadd_rn(__fmul_rn(dx, dx), __fmul_rn(dy, dy)),
                     __fmul_rn(dz, dz));
}

__device__ __forceinline__ int clampi(int v, int lo, int hi) {
    return v < lo ? lo : (v > hi ? hi : v);
}

__device__ __forceinline__ void binCoords(float x, float y, float z,
                                          float invXY, float invZ,
                                          int& bx, int& by, int& bz) {
    bx = clampi((int)floorf(__fmul_rn(__fadd_rn(x, 4.5f), invXY)), 0, NBX - 1);
    by = clampi((int)floorf(__fmul_rn(__fadd_rn(y, 4.5f), invXY)), 0, NBX - 1);
    bz = clampi((int)floorf(__fmul_rn(__fadd_rn(z, 4.0f), invZ)),  0, NBZ - 1);
}

__device__ __forceinline__ int blockScanExcl(int cnt, int* wsum, int tid) {
    int lane = tid & 31, wid = tid >> 5;
    int v = cnt;
    for (int o = 1; o < 32; o <<= 1) {
        int nn = __shfl_up_sync(0xFFFFFFFFu, v, o);
        if (lane >= o) v += nn;
    }
    if (lane == 31) wsum[wid] = v;
    __syncthreads();
    if (wid == 0) {
        int w = wsum[lane];
        for (int o = 1; o < 32; o <<= 1) {
            int nn = __shfl_up_sync(0xFFFFFFFFu, w, o);
            if (lane >= o) w += nn;
        }
        wsum[lane] = w;
    }
    __syncthreads();
    return v - cnt + (wid ? wsum[wid - 1] : 0);
}

__device__ __forceinline__ void gridBarrier(int tid, int nblocks) {
    __threadfence();
    __syncthreads();
    if (tid == 0) {
        unsigned s0 = atomicAdd(&g_sense, 0u);
        unsigned c = atomicAdd(&g_count, 1u);
        if (c == (unsigned)(nblocks - 1)) {
            g_count = 0u;
            __threadfence();
            atomicAdd(&g_sense, 1u);
        } else {
            while (atomicAdd(&g_sense, 0u) == s0) __nanosleep(64);
        }
    }
    __syncthreads();
    __threadfence();
}

// ---------------------------------------------------------------------------
// Persistent kernel, 64 blocks:
//  A (64): sort 1024-key runs      -> g_run0
//  B (32): merge 1024+1024 -> 2048 -> g_run1
//  C (16): merge 2048+2048 -> regs -> coords + NMS -> out
//  D (8):  matching -> tp/fp/fn
// ---------------------------------------------------------------------------
__global__ void __launch_bounds__(1024, 1) k_fused(const float* __restrict__ pred,
                                                   const float* __restrict__ targ,
                                                   float* __restrict__ out)
{
    extern __shared__ unsigned char sm[];
    __shared__ int wsum[32];

    const int tid = threadIdx.x;
    const int bi = blockIdx.x;
    const int NB = gridDim.x;

    // ======================= STAGE A: sort 1024-runs =======================
    {
        unsigned long long* s = (unsigned long long*)sm;   // [1024]
        const int prob = bi >> 2;      // 0..15
        const int quarter = bi & 3;
        const int t = prob >> 3;
        const int be = prob & 7;
        const int b = be >> 1;
        const int e = be & 1;
        const float* in = (t == 0) ? pred : targ;

        int n = quarter * 1024 + tid;
        int z = n >> 10, x = (n >> 5) & 31, y = n & 31;
        int base = ((((b * 32 + x) * 32 + y) * 4 + z) * 8) + e * 4;
        float conf = in[base + 3];
        unsigned u = __float_as_uint(conf);
        u = (u & 0x80000000u) ? ~u : (u | 0x80000000u);
        unsigned long long v = (((unsigned long long)(~u)) << 32) | (unsigned)n;

        for (int k = 2; k <= 1024; k <<= 1) {
            bool up = ((tid & k) == 0);
            for (int j = k >> 1; j > 0; j >>= 1) {
                unsigned long long p;
                if (j >= 32) {
                    s[tid] = v;
                    __syncthreads();
                    p = s[tid ^ j];
                    __syncthreads();
                } else {
                    p = __shfl_xor_sync(0xFFFFFFFFu, v, j);
                }
                bool lower = ((tid & j) == 0);
                bool kmin = (lower == up);
                unsigned long long mn = v < p ? v : p;
                unsigned long long mx = v < p ? p : v;
                v = kmin ? mn : mx;
            }
        }
        g_run0[prob * 4096 + quarter * 1024 + tid] = v;
    }

    gridBarrier(tid, NB);

    // ======================= STAGE B: merge -> 2048 ========================
    if (bi < 32) {
        unsigned long long* sA = (unsigned long long*)sm;              // [1024]
        unsigned long long* sB = (unsigned long long*)(sm + 8 * 1024); // [1024]
        const int prob = bi >> 1;
        const int half = bi & 1;
        const unsigned long long* src = g_run0 + prob * 4096 + half * 2048;
        sA[tid] = src[tid];
        sB[tid] = src[1024 + tid];
        __syncthreads();

        int diag = tid * 2;
        int lo = diag > 1024 ? diag - 1024 : 0;
        int hi = diag < 1024 ? diag : 1024;
        while (lo < hi) {
            int mid = (lo + hi) >> 1;
            if (sA[mid] < sB[diag - 1 - mid]) lo = mid + 1; else hi = mid;
        }
        int ai = lo, bj = diag - lo;
        unsigned long long* dst = g_run1 + prob * 4096 + half * 2048;
        #pragma unroll
        for (int r = 0; r < 2; r++) {
            bool takeA = (bj >= 1024) || (ai < 1024 && sA[ai] <= sB[bj]);
            dst[diag + r] = takeA ? sA[ai++] : sB[bj++];
        }
    }

    gridBarrier(tid, NB);

    // ======================= STAGE C: merge + coords + NMS =================
    if (bi < 16) {
        float* cx = (float*)sm;                                     // [4096] @0
        float* cy = cx + 4096;                                      // @16K
        float* cz = (float*)(sm + 32 * 1024);
        unsigned short* spos = (unsigned short*)(sm + 48 * 1024);
        unsigned char* keepc = (unsigned char*)(sm + 56 * 1024);
        unsigned char* fullk = (unsigned char*)(sm + 60 * 1024);
        unsigned long long* mat = (unsigned long long*)(sm + 64 * 1024);
        unsigned long long* sA2 = (unsigned long long*)(sm + 66 * 1024);  // [2048]
        unsigned long long* sB2 = (unsigned long long*)(sm + 82 * 1024);  // [2048]
        unsigned int* binCnt = (unsigned int*)(sm + 66 * 1024);     // alias after merge
        unsigned int* binStart = (unsigned int*)(sm + 98 * 1024);
        unsigned short* binPts = (unsigned short*)(sm + 130 * 1024);

        __shared__ unsigned long long supp;

        const int prob = bi;
        const int t = prob >> 3;
        const int be = prob & 7;
        const int b = be >> 1;
        const int e = be & 1;
        const float* in = (t == 0) ? pred : targ;
        const float de = (e == 0) ? (float)(0.74 * 1.4) : (float)(0.528 * 1.4);
        const float dd = __fmul_rn(de, de);
        const float cellXY = fmaxf(de, 1.02f);
        const float invXY = 1.0f / cellXY;
        const float invZ = 1.0f / 1.3125f;

        __syncthreads();   // smem reuse fence
        {
            const unsigned long long* src = g_run1 + prob * 4096;
            sA2[tid] = src[tid];
            sA2[1024 + tid] = src[1024 + tid];
            sB2[tid] = src[2048 + tid];
            sB2[1024 + tid] = src[3072 + tid];
        }
        __syncthreads();

        // merge-path: thread tid produces sorted elements 4*tid .. 4*tid+3
        unsigned long long myk[4];
        {
            int diag = tid * 4;
            int lo = diag > 2048 ? diag - 2048 : 0;
            int hi = diag < 2048 ? diag : 2048;
            while (lo < hi) {
                int mid = (lo + hi) >> 1;
                if (sA2[mid] < sB2[diag - 1 - mid]) lo = mid + 1; else hi = mid;
            }
            int ai = lo, bj = diag - lo;
            #pragma unroll
            for (int r = 0; r < 4; r++) {
                bool takeA = (bj >= 2048) || (ai < 2048 && sA2[ai] <= sB2[bj]);
                myk[r] = takeA ? sA2[ai++] : sB2[bj++];
            }
        }

        // ---- coords + write Pc/Tc + compact valid ----
        float rx[4], ry[4], rz[4];
        int vflag[4]; int cnt = 0;
        for (int q = 0; q < 4; q++) {
            int n = (int)(myk[q] & 0xFFFFFFFFull);
            int z = n >> 10, x = (n >> 5) & 31, y = n & 31;
            int base = ((((b * 32 + x) * 32 + y) * 4 + z) * 8) + e * 4;
            float4 vv = *(const float4*)(in + base);
            float c0 = __fmul_rn(__fadd_rn(vv.z, (float)z), 0.75f);
            float c1 = __fmul_rn(__fadd_rn(vv.x, (float)x), 0.78125f);
            float c2 = __fmul_rn(__fadd_rn(vv.y, (float)y), 0.78125f);
            rx[q] = c0; ry[q] = c1; rz[q] = c2;
            vflag[q] = (vv.w > 0.5f) ? 1 : 0;
            cnt += vflag[q];
            int s = tid * 4 + q;
            int ob = (t ? OFF_TC : 0) + ((b * 2 + e) * 4096 + s) * 3;
            out[ob + 0] = c0; out[ob + 1] = c1; out[ob + 2] = c2;
        }

        int excl = blockScanExcl(cnt, wsum, tid);   // barriers ensure merge reads done
        int m = wsum[31];

        for (int q = 0; q < 4; q++) {
            if (vflag[q]) {
                cx[excl] = rx[q]; cy[excl] = ry[q]; cz[excl] = rz[q];
                spos[excl] = (unsigned short)(tid * 4 + q);
                excl++;
            }
        }
        for (int i = tid; i < NBX * NBX * NBZ; i += NTH) binCnt[i] = 0;
        __syncthreads();

        // ---- build bins ----
        for (int ci = tid; ci < m; ci += NTH) {
            int bx, by, bz;
            binCoords(cx[ci], cy[ci], cz[ci], invXY, invZ, bx, by, bz);
            atomicAdd(&binCnt[(bz * NBX + by) * NBX + bx], 1u);
        }
        __syncthreads();
        {
            int base8 = tid * 8;
            int loc[8]; int s = 0;
            for (int k2 = 0; k2 < 8; k2++) { loc[k2] = s; s += (int)binCnt[base8 + k2]; }
            int ex = blockScanExcl(s, wsum, tid);
            for (int k2 = 0; k2 < 8; k2++) binStart[base8 + k2] = (unsigned)(ex + loc[k2]);
        }
        __syncthreads();
        for (int i = tid; i < NBX * NBX * NBZ; i += NTH) binCnt[i] = 0;
        __syncthreads();
        for (int ci = tid; ci < m; ci += NTH) {
            int bx, by, bz;
            binCoords(cx[ci], cy[ci], cz[ci], invXY, invZ, bx, by, bz);
            int bb = (bz * NBX + by) * NBX + bx;
            unsigned off = atomicAdd(&binCnt[bb], 1u);
            binPts[binStart[bb] + off] = (unsigned short)ci;
        }
        __syncthreads();

        // ---- chunked greedy NMS ----
        int nchunks = (m + 63) >> 6;
        for (int c = 0; c < nchunks; c++) {
            int cb = c * 64;
            int cc = min(64, m - cb);
            if (tid == 0) supp = 0ull;
            if (tid < 64) mat[tid] = 0ull;
            __syncthreads();

            int jj = tid >> 4, sub = tid & 15;
            if (jj < cc) {
                int j = cb + jj;
                float px = cx[j], py = cy[j], pz = cz[j];
                int bx, by, bz;
                binCoords(px, py, pz, invXY, invZ, bx, by, bz);
                bool suppressed = false;
                for (int nb = sub; nb < 27; nb += 16) {
                    int dxb = nb % 3 - 1, dyb = (nb / 3) % 3 - 1, dzb = nb / 9 - 1;
                    int X = bx + dxb, Y = by + dyb, Z = bz + dzb;
                    if (X < 0 || X >= NBX || Y < 0 || Y >= NBX || Z < 0 || Z >= NBZ) continue;
                    int bb = (Z * NBX + Y) * NBX + X;
                    unsigned st = binStart[bb], cn = binCnt[bb];
                    for (unsigned p = 0; p < cn; p++) {
                        int a = binPts[st + p];
                        if (a >= j) continue;
                        float d2 = dist2(px, py, pz, cx[a], cy[a], cz[a]);
                        if (d2 < dd) {
                            if (a < cb) { if (keepc[a]) suppressed = true; }
                            else atomicOr(&mat[a - cb], 1ull << jj);
                        }
                    }
                }
                if (suppressed) atomicOr(&supp, 1ull << jj);
            }
            __syncthreads();

            if (tid == 0) {
                unsigned long long s = supp;
                #pragma unroll
                for (int q = 0; q < 64; q++) {
                    unsigned long long mj = mat[q];
                    bool kp = !((s >> q) & 1ull);
                    if (kp) s |= mj;
                    if (q < cc) keepc[cb + q] = kp ? 1 : 0;
                }
            }
            __syncthreads();
        }

        // ---- scatter keep, write mask ----
        for (int q = 0; q < 4; q++) fullk[tid * 4 + q] = 0;
        __syncthreads();
        for (int ci = tid; ci < m; ci += NTH) fullk[spos[ci]] = keepc[ci];
        __syncthreads();
        int kb = (t ? OFF_KT : OFF_KP) + (b * 2 + e) * 4096;
        for (int q = 0; q < 4; q++) {
            int s = tid * 4 + q;
            out[kb + s] = (float)fullk[s];
        }
    }

    gridBarrier(tid, NB);
    if (bi >= 8) return;

    // ======================= STAGE D: matching =============================
    {
        float* cpx = (float*)sm;
        float* cpy = (float*)(sm + 8 * 1024);
        float* cpz = (float*)(sm + 16 * 1024);
        float* ctx = (float*)(sm + 24 * 1024);
        float* cty = (float*)(sm + 32 * 1024);
        float* ctz = (float*)(sm + 40 * 1024);
        unsigned short* ppos = (unsigned short*)(sm + 48 * 1024);
        unsigned short* tpos = (unsigned short*)(sm + 52 * 1024);
        unsigned int* binCnt = (unsigned int*)(sm + 56 * 1024);
        unsigned int* binStart = (unsigned int*)(sm + 88 * 1024);
        unsigned short* binPts = (unsigned short*)(sm + 120 * 1024);
        unsigned char* candCnt = (unsigned char*)(sm + 124 * 1024);
        unsigned short* cand = (unsigned short*)(sm + 126 * 1024);
        unsigned char* tpF = (unsigned char*)(sm + 174 * 1024);
        unsigned char* mtF = (unsigned char*)(sm + 178 * 1024);
        unsigned int* taken = (unsigned int*)(sm + 182 * 1024);
        unsigned int* minIdx = (unsigned int*)(sm + 56 * 1024);   // alias binCnt
        unsigned char* finP = (unsigned char*)(sm + 88 * 1024);   // alias binStart

        __shared__ int cntP, cntT;
        __shared__ int remaining;

        const int be = bi;
        const int b = be >> 1, e = be & 1;
        const float de = (e == 0) ? (float)(0.74 * 1.4) : (float)(0.528 * 1.4);
        const float dd = __fmul_rn(de, de);
        const float cellXY = fmaxf(de, 1.02f);
        const float invXY = 1.0f / cellXY;
        const float invZ = 1.0f / 1.3125f;

        const int pcBase = (b * 2 + e) * 4096 * 3;
        const int tcBase = OFF_TC + pcBase;
        const int kpBase = OFF_KP + (b * 2 + e) * 4096;
        const int ktBase = OFF_KT + (b * 2 + e) * 4096;

        __syncthreads();   // smem reuse fence

        // ---- compact kept preds ----
        {
            float rx[4], ry[4], rz[4]; int f[4]; int cnt = 0;
            for (int q = 0; q < 4; q++) {
                int s = tid * 4 + q;
                int kp = (out[kpBase + s] > 0.5f) ? 1 : 0;
                f[q] = kp; cnt += kp;
                if (kp) {
                    rx[q] = out[pcBase + s * 3 + 0];
                    ry[q] = out[pcBase + s * 3 + 1];
                    rz[q] = out[pcBase + s * 3 + 2];
                }
            }
            int excl = blockScanExcl(cnt, wsum, tid);
            if (tid == 0) cntP = wsum[31];
            for (int q = 0; q < 4; q++) {
                if (f[q] && excl < 2048) {
                    cpx[excl] = rx[q]; cpy[excl] = ry[q]; cpz[excl] = rz[q];
                    ppos[excl] = (unsigned short)(tid * 4 + q);
                    excl++;
                } else if (f[q]) excl++;
            }
            __syncthreads();
        }
        // ---- compact kept targets ----
        {
            float rx[4], ry[4], rz[4]; int f[4]; int cnt = 0;
            for (int q = 0; q < 4; q++) {
                int s = tid * 4 + q;
                int kt = (out[ktBase + s] > 0.5f) ? 1 : 0;
                f[q] = kt; cnt += kt;
                if (kt) {
                    rx[q] = out[tcBase + s * 3 + 0];
                    ry[q] = out[tcBase + s * 3 + 1];
                    rz[q] = out[tcBase + s * 3 + 2];
                }
            }
            int excl = blockScanExcl(cnt, wsum, tid);
            if (tid == 0) cntT = wsum[31];
            for (int q = 0; q < 4; q++) {
                if (f[q] && excl < 2048) {
                    ctx[excl] = rx[q]; cty[excl] = ry[q]; ctz[excl] = rz[q];
                    tpos[excl] = (unsigned short)(tid * 4 + q);
                    excl++;
                } else if (f[q]) excl++;
            }
        }
        for (int i = tid; i < NBX * NBX * NBZ; i += NTH) binCnt[i] = 0;
        if (tid < 64) taken[tid] = 0u;
        if (tid == 0) remaining = 0;
        for (int q = 0; q < 4; q++) { tpF[tid * 4 + q] = 0; mtF[tid * 4 + q] = 0; }
        __syncthreads();

        const int KP = min(cntP, 2048), KT = min(cntT, 2048);

        // ---- bin kept targets ----
        for (int ci = tid; ci < KT; ci += NTH) {
            int bx, by, bz;
            binCoords(ctx[ci], cty[ci], ctz[ci], invXY, invZ, bx, by, bz);
            atomicAdd(&binCnt[(bz * NBX + by) * NBX + bx], 1u);
        }
        __syncthreads();
        {
            int base8 = tid * 8;
            int loc[8]; int s = 0;
            for (int k2 = 0; k2 < 8; k2++) { loc[k2] = s; s += (int)binCnt[base8 + k2]; }
            int ex = blockScanExcl(s, wsum, tid);
            for (int k2 = 0; k2 < 8; k2++) binStart[base8 + k2] = (unsigned)(ex + loc[k2]);
        }
        __syncthreads();
        for (int i = tid; i < NBX * NBX * NBZ; i += NTH) binCnt[i] = 0;
        __syncthreads();
        for (int ci = tid; ci < KT; ci += NTH) {
            int bx, by, bz;
            binCoords(ctx[ci], cty[ci], ctz[ci], invXY, invZ, bx, by, bz);
            int bb = (bz * NBX + by) * NBX + bx;
            unsigned off = atomicAdd(&binCnt[bb], 1u);
            binPts[binStart[bb] + off] = (unsigned short)ci;
        }
        __syncthreads();

        // ---- build per-pred sorted candidate lists ----
        for (int ci = tid; ci < KP; ci += NTH) {
            float px = cpx[ci], py = cpy[ci], pz = cpz[ci];
            int bx, by, bz;
            binCoords(px, py, pz, invXY, invZ, bx, by, bz);
            unsigned short* cl = cand + ci * CAP;
            int nc = 0;
            for (int nb = 0; nb < 27; nb++) {
                int dxb = nb % 3 - 1, dyb = (nb / 3) % 3 - 1, dzb = nb / 9 - 1;
                int X = bx + dxb, Y = by + dyb, Z = bz + dzb;
                if (X < 0 || X >= NBX || Y < 0 || Y >= NBX || Z < 0 || Z >= NBZ) continue;
                int bb = (Z * NBX + Y) * NBX + X;
                unsigned st = binStart[bb], cn = binCnt[bb];
                for (unsigned p = 0; p < cn; p++) {
                    int a = binPts[st + p];
                    float d2 = dist2(px, py, pz, ctx[a], cty[a], ctz[a]);
                    if (d2 < dd) {
                        if (nc < CAP) {
                            int k2 = nc;
                            while (k2 > 0 && cl[k2 - 1] > a) { cl[k2] = cl[k2 - 1]; k2--; }
                            cl[k2] = (unsigned short)a;
                            nc++;
                        } else if (a < cl[CAP - 1]) {
                            int k2 = CAP - 1;
                            while (k2 > 0 && cl[k2 - 1] > a) { cl[k2] = cl[k2 - 1]; k2--; }
                            cl[k2] = (unsigned short)a;
                        }
                    }
                }
            }
            candCnt[ci] = (unsigned char)nc;
        }
        __syncthreads();     // bins dead; finP aliases binStart

        // pre-finalize preds with no candidates
        {
            int act = 0;
            for (int i = tid; i < KP; i += NTH) {
                int a = (candCnt[i] > 0) ? 1 : 0;
                finP[i] = (unsigned char)(1 - a);
                act += a;
            }
            if (act) atomicAdd(&remaining, act);
        }
        __syncthreads();

        // ---- wave-parallel greedy resolution ----
        while (true) {
            if (remaining <= 0) break;
            for (int t2 = tid; t2 < KT; t2 += NTH) minIdx[t2] = 0x7FFFFFFFu;
            __syncthreads();
            for (int i = tid; i < KP; i += NTH) {
                if (!finP[i]) {
                    int nc = candCnt[i];
                    const unsigned short* cl = cand + i * CAP;
                    for (int k2 = 0; k2 < nc; k2++)
                        atomicMin(&minIdx[cl[k2]], (unsigned)i);
                }
            }
            __syncthreads();
            for (int i = tid; i < KP; i += NTH) {
                if (!finP[i]) {
                    int nc = candCnt[i];
                    const unsigned short* cl = cand + i * CAP;
                    bool ok = true;
                    for (int k2 = 0; k2 < nc; k2++)
                        if (minIdx[cl[k2]] < (unsigned)i) { ok = false; break; }
                    if (ok) {
                        for (int k2 = 0; k2 < nc; k2++) {
                            int j = cl[k2];
                            if (!((taken[j >> 5] >> (j & 31)) & 1u)) {
                                atomicOr(&taken[j >> 5], 1u << (j & 31));
                                tpF[ppos[i]] = 1;
                                mtF[tpos[j]] = 1;
                                break;
                            }
                        }
                        finP[i] = 1;
                        atomicSub(&remaining, 1);
                    }
                }
            }
            __syncthreads();
        }

        // ---- write tp/fp/fn ----
        const int tpB = OFF_TP + (b * 2 + e) * 4096;
        const int fpB = OFF_FP + (b * 2 + e) * 4096;
        const int fnB = OFF_FN + (b * 2 + e) * 4096;
        for (int q = 0; q < 4; q++) {
            int s = tid * 4 + q;
            int tp = tpF[s];
            int kp = (out[kpBase + s] > 0.5f) ? 1 : 0;
            int kt = (out[ktBase + s] > 0.5f) ? 1 : 0;
            out[tpB + s] = (float)tp;
            out[fpB + s] = (kp && !tp) ? 1.0f : 0.0f;
            out[fnB + s] = (kt && !mtF[s]) ? 1.0f : 0.0f;
        }
    }
}

// ---------------------------------------------------------------------------
extern "C" void kernel_launch(void* const* d_in, const int* in_sizes, int n_in,
                              void* d_out, int out_size)
{
    const float* pred = (const float*)d_in[0];
    const float* targ = (const float*)d_in[1];
    float* out = (float*)d_out;

    cudaFuncSetAttribute(k_fused, cudaFuncAttributeMaxDynamicSharedMemorySize, 185 * 1024);
    k_fused<<<64, NTH, 184 * 1024>>>(pred, targ, out);
}

// round 6
// speedup vs baseline: 4.7645x; 1.4056x over previous
#include <cuda_runtime.h>
#include <cstdint>

#define NPTS 4096
#define NTH  1024

// d_out float32 layout:
//   Pc [4][2][4096][3] @0, Tc @98304, keepP @196608, keepT @229376,
//   tp @262144, fp @294912, fn @327680
#define OFF_TC 98304
#define OFF_KP 196608
#define OFF_KT 229376
#define OFF_TP 262144
#define OFF_FP 294912
#define OFF_FN 327680

#define NBX 32
#define NBZ 8
#define CAP 12
#define NNCAP 16
#define MAXV 2048

__device__ unsigned g_sense = 0;
__device__ unsigned g_count = 0;
__device__ unsigned long long g_run0[16 * 4096];
__device__ unsigned long long g_run1[16 * 4096];

__device__ __forceinline__ float dist2(float ax, float ay, float az,
                                       float bx, float by, float bz) {
    float dx = __fadd_rn(ax, -bx);
    float dy = __fadd_rn(ay, -by);
    float dz = __fadd_rn(az, -bz);
    return __fadd_rn(__fadd_rn(__fmul_rn(dx, dx), __fmul_rn(dy, dy)),
                     __fmul_rn(dz, dz));
}

__device__ __forceinline__ int clampi(int v, int lo, int hi) {
    return v < lo ? lo : (v > hi ? hi : v);
}

__device__ __forceinline__ void binCoords(float x, float y, float z,
                                          float invXY, float invZ,
                                          int& bx, int& by, int& bz) {
    bx = clampi((int)floorf(__fmul_rn(__fadd_rn(x, 4.5f), invXY)), 0, NBX - 1);
    by = clampi((int)floorf(__fmul_rn(__fadd_rn(y, 4.5f), invXY)), 0, NBX - 1);
    bz = clampi((int)floorf(__fmul_rn(__fadd_rn(z, 4.0f), invZ)),  0, NBZ - 1);
}

__device__ __forceinline__ int blockScanExcl(int cnt, int* wsum, int tid) {
    int lane = tid & 31, wid = tid >> 5;
    int v = cnt;
    for (int o = 1; o < 32; o <<= 1) {
        int nn = __shfl_up_sync(0xFFFFFFFFu, v, o);
        if (lane >= o) v += nn;
    }
    if (lane == 31) wsum[wid] = v;
    __syncthreads();
    if (wid == 0) {
        int w = wsum[lane];
        for (int o = 1; o < 32; o <<= 1) {
            int nn = __shfl_up_sync(0xFFFFFFFFu, w, o);
            if (lane >= o) w += nn;
        }
        wsum[lane] = w;
    }
    __syncthreads();
    return v - cnt + (wid ? wsum[wid - 1] : 0);
}

__device__ __forceinline__ void gridBarrier(int tid, int nblocks) {
    __threadfence();
    __syncthreads();
    if (tid == 0) {
        unsigned s0 = atomicAdd(&g_sense, 0u);
        unsigned c = atomicAdd(&g_count, 1u);
        if (c == (unsigned)(nblocks - 1)) {
            g_count = 0u;
            __threadfence();
            atomicAdd(&g_sense, 1u);
        } else {
            while (atomicAdd(&g_sense, 0u) == s0) __nanosleep(64);
        }
    }
    __syncthreads();
    __threadfence();
}

// ---------------------------------------------------------------------------
// Persistent kernel, 64 blocks:
//  A (64): sort 1024-key runs      -> g_run0
//  B (32): merge 1024+1024 -> 2048 -> g_run1
//  C (16): merge 2048+2048 -> coords -> one-pass neighbor lists -> wave NMS
//  D (8):  matching -> tp/fp/fn
// ---------------------------------------------------------------------------
__global__ void __launch_bounds__(1024, 1) k_fused(const float* __restrict__ pred,
                                                   const float* __restrict__ targ,
                                                   float* __restrict__ out)
{
    extern __shared__ unsigned char sm[];
    __shared__ int wsum[32];

    const int tid = threadIdx.x;
    const int bi = blockIdx.x;
    const int NB = gridDim.x;

    // ======================= STAGE A: sort 1024-runs =======================
    {
        unsigned long long* s = (unsigned long long*)sm;   // [1024]
        const int prob = bi >> 2;      // 0..15
        const int quarter = bi & 3;
        const int t = prob >> 3;
        const int be = prob & 7;
        const int b = be >> 1;
        const int e = be & 1;
        const float* in = (t == 0) ? pred : targ;

        int n = quarter * 1024 + tid;
        int z = n >> 10, x = (n >> 5) & 31, y = n & 31;
        int base = ((((b * 32 + x) * 32 + y) * 4 + z) * 8) + e * 4;
        float conf = in[base + 3];
        unsigned u = __float_as_uint(conf);
        u = (u & 0x80000000u) ? ~u : (u | 0x80000000u);
        unsigned long long v = (((unsigned long long)(~u)) << 32) | (unsigned)n;

        for (int k = 2; k <= 1024; k <<= 1) {
            bool up = ((tid & k) == 0);
            for (int j = k >> 1; j > 0; j >>= 1) {
                unsigned long long p;
                if (j >= 32) {
                    s[tid] = v;
                    __syncthreads();
                    p = s[tid ^ j];
                    __syncthreads();
                } else {
                    p = __shfl_xor_sync(0xFFFFFFFFu, v, j);
                }
                bool lower = ((tid & j) == 0);
                bool kmin = (lower == up);
                unsigned long long mn = v < p ? v : p;
                unsigned long long mx = v < p ? p : v;
                v = kmin ? mn : mx;
            }
        }
        g_run0[prob * 4096 + quarter * 1024 + tid] = v;
    }

    gridBarrier(tid, NB);

    // ======================= STAGE B: merge -> 2048 ========================
    if (bi < 32) {
        unsigned long long* sA = (unsigned long long*)sm;              // [1024]
        unsigned long long* sB = (unsigned long long*)(sm + 8 * 1024); // [1024]
        const int prob = bi >> 1;
        const int half = bi & 1;
        const unsigned long long* src = g_run0 + prob * 4096 + half * 2048;
        sA[tid] = src[tid];
        sB[tid] = src[1024 + tid];
        __syncthreads();

        int diag = tid * 2;
        int lo = diag > 1024 ? diag - 1024 : 0;
        int hi = diag < 1024 ? diag : 1024;
        while (lo < hi) {
            int mid = (lo + hi) >> 1;
            if (sA[mid] < sB[diag - 1 - mid]) lo = mid + 1; else hi = mid;
        }
        int ai = lo, bj = diag - lo;
        unsigned long long* dst = g_run1 + prob * 4096 + half * 2048;
        #pragma unroll
        for (int r = 0; r < 2; r++) {
            bool takeA = (bj >= 1024) || (ai < 1024 && sA[ai] <= sB[bj]);
            dst[diag + r] = takeA ? sA[ai++] : sB[bj++];
        }
    }

    gridBarrier(tid, NB);

    // ============ STAGE C: merge + coords + nbr lists + wave NMS ===========
    if (bi < 16) {
        float* cx = (float*)sm;                                      // 8KB
        float* cy = (float*)(sm + 8 * 1024);
        float* cz = (float*)(sm + 16 * 1024);
        unsigned short* spos = (unsigned short*)(sm + 24 * 1024);    // 4KB
        unsigned char* fullk = (unsigned char*)(sm + 28 * 1024);     // 4KB
        unsigned long long* sA2 = (unsigned long long*)(sm + 32 * 1024); // 16KB
        unsigned long long* sB2 = (unsigned long long*)(sm + 48 * 1024); // 16KB
        unsigned short* nbr = (unsigned short*)(sm + 32 * 1024);     // 64KB (alias sA2/sB2, used after merge)
        unsigned int* binCnt = (unsigned int*)(sm + 96 * 1024);      // 32KB
        unsigned int* binStart = (unsigned int*)(sm + 128 * 1024);   // 32KB
        unsigned short* binPts = (unsigned short*)(sm + 160 * 1024); // 4KB
        unsigned char* nbrCnt = (unsigned char*)(sm + 164 * 1024);   // 2KB
        unsigned char* state = (unsigned char*)(sm + 166 * 1024);    // 2KB

        __shared__ int remaining;

        const int prob = bi;
        const int t = prob >> 3;
        const int be = prob & 7;
        const int b = be >> 1;
        const int e = be & 1;
        const float* in = (t == 0) ? pred : targ;
        const float de = (e == 0) ? (float)(0.74 * 1.4) : (float)(0.528 * 1.4);
        const float dd = __fmul_rn(de, de);
        const float cellXY = fmaxf(de, 1.02f);
        const float invXY = 1.0f / cellXY;
        const float invZ = 1.0f / 1.3125f;

        __syncthreads();   // smem reuse fence
        {
            const unsigned long long* src = g_run1 + prob * 4096;
            sA2[tid] = src[tid];
            sA2[1024 + tid] = src[1024 + tid];
            sB2[tid] = src[2048 + tid];
            sB2[1024 + tid] = src[3072 + tid];
        }
        __syncthreads();

        // merge-path: thread tid produces sorted elements 4*tid .. 4*tid+3
        unsigned long long myk[4];
        {
            int diag = tid * 4;
            int lo = diag > 2048 ? diag - 2048 : 0;
            int hi = diag < 2048 ? diag : 2048;
            while (lo < hi) {
                int mid = (lo + hi) >> 1;
                if (sA2[mid] < sB2[diag - 1 - mid]) lo = mid + 1; else hi = mid;
            }
            int ai = lo, bj = diag - lo;
            #pragma unroll
            for (int r = 0; r < 4; r++) {
                bool takeA = (bj >= 2048) || (ai < 2048 && sA2[ai] <= sB2[bj]);
                myk[r] = takeA ? sA2[ai++] : sB2[bj++];
            }
        }

        // ---- coords + write Pc/Tc + compact valid ----
        float rx[4], ry[4], rz[4];
        int vflag[4]; int cnt = 0;
        for (int q = 0; q < 4; q++) {
            int n = (int)(myk[q] & 0xFFFFFFFFull);
            int z = n >> 10, x = (n >> 5) & 31, y = n & 31;
            int base = ((((b * 32 + x) * 32 + y) * 4 + z) * 8) + e * 4;
            float4 vv = *(const float4*)(in + base);
            float c0 = __fmul_rn(__fadd_rn(vv.z, (float)z), 0.75f);
            float c1 = __fmul_rn(__fadd_rn(vv.x, (float)x), 0.78125f);
            float c2 = __fmul_rn(__fadd_rn(vv.y, (float)y), 0.78125f);
            rx[q] = c0; ry[q] = c1; rz[q] = c2;
            vflag[q] = (vv.w > 0.5f) ? 1 : 0;
            cnt += vflag[q];
            int s = tid * 4 + q;
            int ob = (t ? OFF_TC : 0) + ((b * 2 + e) * 4096 + s) * 3;
            out[ob + 0] = c0; out[ob + 1] = c1; out[ob + 2] = c2;
        }

        int excl = blockScanExcl(cnt, wsum, tid);   // internal barriers fence sA2/sB2 reads
        int m = min(wsum[31], MAXV);

        for (int q = 0; q < 4; q++) {
            if (vflag[q]) {
                if (excl < MAXV) {
                    cx[excl] = rx[q]; cy[excl] = ry[q]; cz[excl] = rz[q];
                    spos[excl] = (unsigned short)(tid * 4 + q);
                }
                excl++;
            }
        }
        for (int i = tid; i < NBX * NBX * NBZ; i += NTH) binCnt[i] = 0;
        for (int q = 0; q < 4; q++) fullk[tid * 4 + q] = 0;
        __syncthreads();

        // ---- build bins over compacted valid points ----
        for (int ci = tid; ci < m; ci += NTH) {
            int bx, by, bz;
            binCoords(cx[ci], cy[ci], cz[ci], invXY, invZ, bx, by, bz);
            atomicAdd(&binCnt[(bz * NBX + by) * NBX + bx], 1u);
        }
        __syncthreads();
        {
            int base8 = tid * 8;
            int loc[8]; int s = 0;
            for (int k2 = 0; k2 < 8; k2++) { loc[k2] = s; s += (int)binCnt[base8 + k2]; }
            int ex = blockScanExcl(s, wsum, tid);
            for (int k2 = 0; k2 < 8; k2++) binStart[base8 + k2] = (unsigned)(ex + loc[k2]);
        }
        __syncthreads();
        for (int i = tid; i < NBX * NBX * NBZ; i += NTH) binCnt[i] = 0;
        __syncthreads();
        for (int ci = tid; ci < m; ci += NTH) {
            int bx, by, bz;
            binCoords(cx[ci], cy[ci], cz[ci], invXY, invZ, bx, by, bz);
            int bb = (bz * NBX + by) * NBX + bx;
            unsigned off = atomicAdd(&binCnt[bb], 1u);
            binPts[binStart[bb] + off] = (unsigned short)ci;
        }
        __syncthreads();

        // ---- ONE-PASS earlier-neighbor list build ----
        if (tid == 0) remaining = 0;
        __syncthreads();
        {
            int undec = 0;
            for (int ci = tid; ci < m; ci += NTH) {
                float px = cx[ci], py = cy[ci], pz = cz[ci];
                int bx, by, bz;
                binCoords(px, py, pz, invXY, invZ, bx, by, bz);
                int nc = 0;
                #pragma unroll
                for (int dzb = -1; dzb <= 1; dzb++) {
                    int Z = bz + dzb;
                    if (Z < 0 || Z >= NBZ) continue;
                    #pragma unroll
                    for (int dyb = -1; dyb <= 1; dyb++) {
                        int Y = by + dyb;
                        if (Y < 0 || Y >= NBX) continue;
                        #pragma unroll
                        for (int dxb = -1; dxb <= 1; dxb++) {
                            int X = bx + dxb;
                            if (X < 0 || X >= NBX) continue;
                            int bb = (Z * NBX + Y) * NBX + X;
                            unsigned st = binStart[bb], cn = binCnt[bb];
                            for (unsigned p = 0; p < cn; p++) {
                                int a = binPts[st + p];
                                if (a < ci) {
                                    float d2 = dist2(px, py, pz, cx[a], cy[a], cz[a]);
                                    if (d2 < dd && nc < NNCAP)
                                        nbr[ci * NNCAP + nc++] = (unsigned short)a;
                                }
                            }
                        }
                    }
                }
                nbrCnt[ci] = (unsigned char)nc;
                int st0 = (nc == 0) ? 1 : 0;
                state[ci] = (unsigned char)st0;
                undec += (st0 == 0);
            }
            if (undec) atomicAdd(&remaining, undec);
        }
        __syncthreads();

        // ---- wave NMS resolution (exact sequential semantics) ----
        while (true) {
            if (remaining <= 0) break;
            int dec = 0;
            for (int ci = tid; ci < m; ci += NTH) {
                if (state[ci] == 0) {
                    int nc = nbrCnt[ci];
                    bool anyK = false, allS = true;
                    for (int k2 = 0; k2 < nc; k2++) {
                        unsigned char s2 = state[nbr[ci * NNCAP + k2]];
                        anyK |= (s2 == 1);
                        allS &= (s2 == 2);
                    }
                    if (anyK) { state[ci] = 2; dec++; }
                    else if (allS) { state[ci] = 1; dec++; }
                }
            }
            if (dec) atomicSub(&remaining, dec);
            __syncthreads();
        }

        // ---- scatter keep, write mask ----
        for (int ci = tid; ci < m; ci += NTH)
            fullk[spos[ci]] = (state[ci] == 1) ? 1 : 0;
        __syncthreads();
        int kb = (t ? OFF_KT : OFF_KP) + (b * 2 + e) * 4096;
        for (int q = 0; q < 4; q++) {
            int s = tid * 4 + q;
            out[kb + s] = (float)fullk[s];
        }
    }

    gridBarrier(tid, NB);
    if (bi >= 8) return;

    // ======================= STAGE D: matching =============================
    {
        float* cpx = (float*)sm;
        float* cpy = (float*)(sm + 8 * 1024);
        float* cpz = (float*)(sm + 16 * 1024);
        float* ctx = (float*)(sm + 24 * 1024);
        float* cty = (float*)(sm + 32 * 1024);
        float* ctz = (float*)(sm + 40 * 1024);
        unsigned short* ppos = (unsigned short*)(sm + 48 * 1024);
        unsigned short* tpos = (unsigned short*)(sm + 52 * 1024);
        unsigned int* binCnt = (unsigned int*)(sm + 56 * 1024);
        unsigned int* binStart = (unsigned int*)(sm + 88 * 1024);
        unsigned short* binPts = (unsigned short*)(sm + 120 * 1024);
        unsigned char* candCnt = (unsigned char*)(sm + 124 * 1024);
        unsigned short* cand = (unsigned short*)(sm + 126 * 1024);
        unsigned char* tpF = (unsigned char*)(sm + 174 * 1024);
        unsigned char* mtF = (unsigned char*)(sm + 178 * 1024);
        unsigned int* taken = (unsigned int*)(sm + 182 * 1024);
        unsigned int* minIdx = (unsigned int*)(sm + 56 * 1024);   // alias binCnt
        unsigned char* finP = (unsigned char*)(sm + 88 * 1024);   // alias binStart

        __shared__ int cntP, cntT;
        __shared__ int remaining;

        const int be = bi;
        const int b = be >> 1, e = be & 1;
        const float de = (e == 0) ? (float)(0.74 * 1.4) : (float)(0.528 * 1.4);
        const float dd = __fmul_rn(de, de);
        const float cellXY = fmaxf(de, 1.02f);
        const float invXY = 1.0f / cellXY;
        const float invZ = 1.0f / 1.3125f;

        const int pcBase = (b * 2 + e) * 4096 * 3;
        const int tcBase = OFF_TC + pcBase;
        const int kpBase = OFF_KP + (b * 2 + e) * 4096;
        const int ktBase = OFF_KT + (b * 2 + e) * 4096;

        __syncthreads();   // smem reuse fence

        // ---- compact kept preds ----
        {
            float rx[4], ry[4], rz[4]; int f[4]; int cnt = 0;
            for (int q = 0; q < 4; q++) {
                int s = tid * 4 + q;
                int kp = (out[kpBase + s] > 0.5f) ? 1 : 0;
                f[q] = kp; cnt += kp;
                if (kp) {
                    rx[q] = out[pcBase + s * 3 + 0];
                    ry[q] = out[pcBase + s * 3 + 1];
                    rz[q] = out[pcBase + s * 3 + 2];
                }
            }
            int excl = blockScanExcl(cnt, wsum, tid);
            if (tid == 0) cntP = wsum[31];
            for (int q = 0; q < 4; q++) {
                if (f[q] && excl < 2048) {
                    cpx[excl] = rx[q]; cpy[excl] = ry[q]; cpz[excl] = rz[q];
                    ppos[excl] = (unsigned short)(tid * 4 + q);
                    excl++;
                } else if (f[q]) excl++;
            }
            __syncthreads();
        }
        // ---- compact kept targets ----
        {
            float rx[4], ry[4], rz[4]; int f[4]; int cnt = 0;
            for (int q = 0; q < 4; q++) {
                int s = tid * 4 + q;
                int kt = (out[ktBase + s] > 0.5f) ? 1 : 0;
                f[q] = kt; cnt += kt;
                if (kt) {
                    rx[q] = out[tcBase + s * 3 + 0];
                    ry[q] = out[tcBase + s * 3 + 1];
                    rz[q] = out[tcBase + s * 3 + 2];
                }
            }
            int excl = blockScanExcl(cnt, wsum, tid);
            if (tid == 0) cntT = wsum[31];
            for (int q = 0; q < 4; q++) {
                if (f[q] && excl < 2048) {
                    ctx[excl] = rx[q]; cty[excl] = ry[q]; ctz[excl] = rz[q];
                    tpos[excl] = (unsigned short)(tid * 4 + q);
                    excl++;
                } else if (f[q]) excl++;
            }
        }
        for (int i = tid; i < NBX * NBX * NBZ; i += NTH) binCnt[i] = 0;
        if (tid < 64) taken[tid] = 0u;
        if (tid == 0) remaining = 0;
        for (int q = 0; q < 4; q++) { tpF[tid * 4 + q] = 0; mtF[tid * 4 + q] = 0; }
        __syncthreads();

        const int KP = min(cntP, 2048), KT = min(cntT, 2048);

        // ---- bin kept targets ----
        for (int ci = tid; ci < KT; ci += NTH) {
            int bx, by, bz;
            binCoords(ctx[ci], cty[ci], ctz[ci], invXY, invZ, bx, by, bz);
            atomicAdd(&binCnt[(bz * NBX + by) * NBX + bx], 1u);
        }
        __syncthreads();
        {
            int base8 = tid * 8;
            int loc[8]; int s = 0;
            for (int k2 = 0; k2 < 8; k2++) { loc[k2] = s; s += (int)binCnt[base8 + k2]; }
            int ex = blockScanExcl(s, wsum, tid);
            for (int k2 = 0; k2 < 8; k2++) binStart[base8 + k2] = (unsigned)(ex + loc[k2]);
        }
        __syncthreads();
        for (int i = tid; i < NBX * NBX * NBZ; i += NTH) binCnt[i] = 0;
        __syncthreads();
        for (int ci = tid; ci < KT; ci += NTH) {
            int bx, by, bz;
            binCoords(ctx[ci], cty[ci], ctz[ci], invXY, invZ, bx, by, bz);
            int bb = (bz * NBX + by) * NBX + bx;
            unsigned off = atomicAdd(&binCnt[bb], 1u);
            binPts[binStart[bb] + off] = (unsigned short)ci;
        }
        __syncthreads();

        // ---- build per-pred sorted candidate lists (one pass) ----
        for (int ci = tid; ci < KP; ci += NTH) {
            float px = cpx[ci], py = cpy[ci], pz = cpz[ci];
            int bx, by, bz;
            binCoords(px, py, pz, invXY, invZ, bx, by, bz);
            unsigned short* cl = cand + ci * CAP;
            int nc = 0;
            #pragma unroll
            for (int dzb = -1; dzb <= 1; dzb++) {
                int Z = bz + dzb;
                if (Z < 0 || Z >= NBZ) continue;
                #pragma unroll
                for (int dyb = -1; dyb <= 1; dyb++) {
                    int Y = by + dyb;
                    if (Y < 0 || Y >= NBX) continue;
                    #pragma unroll
                    for (int dxb = -1; dxb <= 1; dxb++) {
                        int X = bx + dxb;
                        if (X < 0 || X >= NBX) continue;
                        int bb = (Z * NBX + Y) * NBX + X;
                        unsigned st = binStart[bb], cn = binCnt[bb];
                        for (unsigned p = 0; p < cn; p++) {
                            int a = binPts[st + p];
                            float d2 = dist2(px, py, pz, ctx[a], cty[a], ctz[a]);
                            if (d2 < dd) {
                                if (nc < CAP) {
                                    int k2 = nc;
                                    while (k2 > 0 && cl[k2 - 1] > a) { cl[k2] = cl[k2 - 1]; k2--; }
                                    cl[k2] = (unsigned short)a;
                                    nc++;
                                } else if (a < cl[CAP - 1]) {
                                    int k2 = CAP - 1;
                                    while (k2 > 0 && cl[k2 - 1] > a) { cl[k2] = cl[k2 - 1]; k2--; }
                                    cl[k2] = (unsigned short)a;
                                }
                            }
                        }
                    }
                }
            }
            candCnt[ci] = (unsigned char)nc;
        }
        __syncthreads();     // bins dead; finP aliases binStart

        // pre-finalize preds with no candidates
        {
            int act = 0;
            for (int i = tid; i < KP; i += NTH) {
                int a = (candCnt[i] > 0) ? 1 : 0;
                finP[i] = (unsigned char)(1 - a);
                act += a;
            }
            if (act) atomicAdd(&remaining, act);
        }
        __syncthreads();

        // ---- wave-parallel greedy resolution ----
        while (true) {
            if (remaining <= 0) break;
            for (int t2 = tid; t2 < KT; t2 += NTH) minIdx[t2] = 0x7FFFFFFFu;
            __syncthreads();
            for (int i = tid; i < KP; i += NTH) {
                if (!finP[i]) {
                    int nc = candCnt[i];
                    const unsigned short* cl = cand + i * CAP;
                    for (int k2 = 0; k2 < nc; k2++)
                        atomicMin(&minIdx[cl[k2]], (unsigned)i);
                }
            }
            __syncthreads();
            for (int i = tid; i < KP; i += NTH) {
                if (!finP[i]) {
                    int nc = candCnt[i];
                    const unsigned short* cl = cand + i * CAP;
                    bool ok = true;
                    for (int k2 = 0; k2 < nc; k2++)
                        if (minIdx[cl[k2]] < (unsigned)i) { ok = false; break; }
                    if (ok) {
                        for (int k2 = 0; k2 < nc; k2++) {
                            int j = cl[k2];
                            if (!((taken[j >> 5] >> (j & 31)) & 1u)) {
                                atomicOr(&taken[j >> 5], 1u << (j & 31));
                                tpF[ppos[i]] = 1;
                                mtF[tpos[j]] = 1;
                                break;
                            }
                        }
                        finP[i] = 1;
                        atomicSub(&remaining, 1);
                    }
                }
            }
            __syncthreads();
        }

        // ---- write tp/fp/fn ----
        const int tpB = OFF_TP + (b * 2 + e) * 4096;
        const int fpB = OFF_FP + (b * 2 + e) * 4096;
        const int fnB = OFF_FN + (b * 2 + e) * 4096;
        for (int q = 0; q < 4; q++) {
            int s = tid * 4 + q;
            int tp = tpF[s];
            int kp = (out[kpBase + s] > 0.5f) ? 1 : 0;
            int kt = (out[ktBase + s] > 0.5f) ? 1 : 0;
            out[tpB + s] = (float)tp;
            out[fpB + s] = (kp && !tp) ? 1.0f : 0.0f;
            out[fnB + s] = (kt && !mtF[s]) ? 1.0f : 0.0f;
        }
    }
}

// ---------------------------------------------------------------------------
extern "C" void kernel_launch(void* const* d_in, const int* in_sizes, int n_in,
                              void* d_out, int out_size)
{
    const float* pred = (const float*)d_in[0];
    const float* targ = (const float*)d_in[1];
    float* out = (float*)d_out;

    cudaFuncSetAttribute(k_fused, cudaFuncAttributeMaxDynamicSharedMemorySize, 185 * 1024);
    k_fused<<<64, NTH, 184 * 1024>>>(pred, targ, out);
}

// round 7
// speedup vs baseline: 4.9209x; 1.0328x over previous
#include <cuda_runtime.h>
#include <cstdint>

#define NPTS 4096
#define NTH  1024

// d_out float32 layout:
//   Pc [4][2][4096][3] @0, Tc @98304, keepP @196608, keepT @229376,
//   tp @262144, fp @294912, fn @327680
#define OFF_TC 98304
#define OFF_KP 196608
#define OFF_KT 229376
#define OFF_TP 262144
#define OFF_FP 294912
#define OFF_FN 327680

#define NBX 32
#define NBZ 8
#define CAP 12
#define NNCAP 16
#define MAXV 2048

__device__ unsigned long long g_run0[16 * 4096];
__device__ unsigned long long g_run1[16 * 4096];
// NMS-kept compact lists per problem (16 = {pred,targ} x {b,e})
__device__ float g_kx[16 * 2048];
__device__ float g_ky[16 * 2048];
__device__ float g_kz[16 * 2048];
__device__ unsigned short g_kpos[16 * 2048];
__device__ int g_kcnt[16];

__device__ __forceinline__ float dist2(float ax, float ay, float az,
                                       float bx, float by, float bz) {
    float dx = __fadd_rn(ax, -bx);
    float dy = __fadd_rn(ay, -by);
    float dz = __fadd_rn(az, -bz);
    return __fadd_rn(__fadd_rn(__fmul_rn(dx, dx), __fmul_rn(dy, dy)),
                     __fmul_rn(dz, dz));
}

__device__ __forceinline__ int clampi(int v, int lo, int hi) {
    return v < lo ? lo : (v > hi ? hi : v);
}

__device__ __forceinline__ void binCoords(float x, float y, float z,
                                          float invXY, float invZ,
                                          int& bx, int& by, int& bz) {
    bx = clampi((int)floorf(__fmul_rn(__fadd_rn(x, 4.5f), invXY)), 0, NBX - 1);
    by = clampi((int)floorf(__fmul_rn(__fadd_rn(y, 4.5f), invXY)), 0, NBX - 1);
    bz = clampi((int)floorf(__fmul_rn(__fadd_rn(z, 4.0f), invZ)),  0, NBZ - 1);
}

__device__ __forceinline__ int blockScanExcl(int cnt, int* wsum, int tid) {
    int lane = tid & 31, wid = tid >> 5;
    int v = cnt;
    for (int o = 1; o < 32; o <<= 1) {
        int nn = __shfl_up_sync(0xFFFFFFFFu, v, o);
        if (lane >= o) v += nn;
    }
    if (lane == 31) wsum[wid] = v;
    __syncthreads();
    if (wid == 0) {
        int w = wsum[lane];
        for (int o = 1; o < 32; o <<= 1) {
            int nn = __shfl_up_sync(0xFFFFFFFFu, w, o);
            if (lane >= o) w += nn;
        }
        wsum[lane] = w;
    }
    __syncthreads();
    return v - cnt + (wid ? wsum[wid - 1] : 0);
}

// ---------------------------------------------------------------------------
// Kernel A (64 blocks): sort 1024-key runs -> g_run0
// ---------------------------------------------------------------------------
__global__ void __launch_bounds__(1024) k_sortA(const float* __restrict__ pred,
                                                const float* __restrict__ targ)
{
    extern __shared__ unsigned char sm[];
    unsigned long long* s = (unsigned long long*)sm;   // [1024]
    const int tid = threadIdx.x;
    const int bi = blockIdx.x;
    const int prob = bi >> 2;
    const int quarter = bi & 3;
    const int t = prob >> 3;
    const int be = prob & 7;
    const int b = be >> 1;
    const int e = be & 1;
    const float* in = (t == 0) ? pred : targ;

    int n = quarter * 1024 + tid;
    int z = n >> 10, x = (n >> 5) & 31, y = n & 31;
    int base = ((((b * 32 + x) * 32 + y) * 4 + z) * 8) + e * 4;
    float conf = in[base + 3];
    unsigned u = __float_as_uint(conf);
    u = (u & 0x80000000u) ? ~u : (u | 0x80000000u);
    unsigned long long v = (((unsigned long long)(~u)) << 32) | (unsigned)n;

    for (int k = 2; k <= 1024; k <<= 1) {
        bool up = ((tid & k) == 0);
        for (int j = k >> 1; j > 0; j >>= 1) {
            unsigned long long p;
            if (j >= 32) {
                s[tid] = v;
                __syncthreads();
                p = s[tid ^ j];
                __syncthreads();
            } else {
                p = __shfl_xor_sync(0xFFFFFFFFu, v, j);
            }
            bool lower = ((tid & j) == 0);
            bool kmin = (lower == up);
            unsigned long long mn = v < p ? v : p;
            unsigned long long mx = v < p ? p : v;
            v = kmin ? mn : mx;
        }
    }
    g_run0[prob * 4096 + quarter * 1024 + tid] = v;
}

// ---------------------------------------------------------------------------
// Kernel B (32 blocks): merge 1024+1024 -> 2048 -> g_run1
// ---------------------------------------------------------------------------
__global__ void __launch_bounds__(1024) k_sortB()
{
    extern __shared__ unsigned char sm[];
    unsigned long long* sA = (unsigned long long*)sm;              // [1024]
    unsigned long long* sB = (unsigned long long*)(sm + 8 * 1024); // [1024]
    const int tid = threadIdx.x;
    const int prob = blockIdx.x >> 1;
    const int half = blockIdx.x & 1;
    const unsigned long long* src = g_run0 + prob * 4096 + half * 2048;
    sA[tid] = src[tid];
    sB[tid] = src[1024 + tid];
    __syncthreads();

    int diag = tid * 2;
    int lo = diag > 1024 ? diag - 1024 : 0;
    int hi = diag < 1024 ? diag : 1024;
    while (lo < hi) {
        int mid = (lo + hi) >> 1;
        if (sA[mid] < sB[diag - 1 - mid]) lo = mid + 1; else hi = mid;
    }
    int ai = lo, bj = diag - lo;
    unsigned long long* dst = g_run1 + prob * 4096 + half * 2048;
    #pragma unroll
    for (int r = 0; r < 2; r++) {
        bool takeA = (bj >= 1024) || (ai < 1024 && sA[ai] <= sB[bj]);
        dst[diag + r] = takeA ? sA[ai++] : sB[bj++];
    }
}

// ---------------------------------------------------------------------------
// Kernel C (16 blocks): merge + coords + neighbor lists + wave NMS
//   -> Pc/Tc + keep masks in out; compact kept lists in g_k*
// ---------------------------------------------------------------------------
__global__ void __launch_bounds__(1024) k_nms(const float* __restrict__ pred,
                                              const float* __restrict__ targ,
                                              float* __restrict__ out)
{
    extern __shared__ unsigned char sm[];
    float* cx = (float*)sm;                                      // 8KB
    float* cy = (float*)(sm + 8 * 1024);
    float* cz = (float*)(sm + 16 * 1024);
    unsigned short* spos = (unsigned short*)(sm + 24 * 1024);    // 4KB
    unsigned char* fullk = (unsigned char*)(sm + 28 * 1024);     // 4KB
    unsigned long long* sA2 = (unsigned long long*)(sm + 32 * 1024); // 16KB
    unsigned long long* sB2 = (unsigned long long*)(sm + 48 * 1024); // 16KB
    unsigned short* nbr = (unsigned short*)(sm + 32 * 1024);     // 64KB alias (post-merge)
    unsigned int* binCnt = (unsigned int*)(sm + 96 * 1024);      // 32KB
    unsigned int* binStart = (unsigned int*)(sm + 128 * 1024);   // 32KB
    unsigned short* binPts = (unsigned short*)(sm + 160 * 1024); // 4KB
    unsigned char* nbrCnt = (unsigned char*)(sm + 164 * 1024);   // 2KB
    unsigned char* state = (unsigned char*)(sm + 166 * 1024);    // 2KB

    __shared__ int wsum[32];
    __shared__ int remaining;

    const int tid = threadIdx.x;
    const int prob = blockIdx.x;
    const int t = prob >> 3;
    const int be = prob & 7;
    const int b = be >> 1;
    const int e = be & 1;
    const float* in = (t == 0) ? pred : targ;
    const float de = (e == 0) ? (float)(0.74 * 1.4) : (float)(0.528 * 1.4);
    const float dd = __fmul_rn(de, de);
    const float cellXY = fmaxf(de, 1.02f);
    const float invXY = 1.0f / cellXY;
    const float invZ = 1.0f / 1.3125f;

    {
        const unsigned long long* src = g_run1 + prob * 4096;
        sA2[tid] = src[tid];
        sA2[1024 + tid] = src[1024 + tid];
        sB2[tid] = src[2048 + tid];
        sB2[1024 + tid] = src[3072 + tid];
    }
    __syncthreads();

    // merge-path: thread tid produces sorted elements 4*tid .. 4*tid+3
    unsigned long long myk[4];
    {
        int diag = tid * 4;
        int lo = diag > 2048 ? diag - 2048 : 0;
        int hi = diag < 2048 ? diag : 2048;
        while (lo < hi) {
            int mid = (lo + hi) >> 1;
            if (sA2[mid] < sB2[diag - 1 - mid]) lo = mid + 1; else hi = mid;
        }
        int ai = lo, bj = diag - lo;
        #pragma unroll
        for (int r = 0; r < 4; r++) {
            bool takeA = (bj >= 2048) || (ai < 2048 && sA2[ai] <= sB2[bj]);
            myk[r] = takeA ? sA2[ai++] : sB2[bj++];
        }
    }

    // ---- coords + write Pc/Tc + compact valid ----
    float rx[4], ry[4], rz[4];
    int vflag[4]; int cnt = 0;
    for (int q = 0; q < 4; q++) {
        int n = (int)(myk[q] & 0xFFFFFFFFull);
        int z = n >> 10, x = (n >> 5) & 31, y = n & 31;
        int base = ((((b * 32 + x) * 32 + y) * 4 + z) * 8) + e * 4;
        float4 vv = *(const float4*)(in + base);
        float c0 = __fmul_rn(__fadd_rn(vv.z, (float)z), 0.75f);
        float c1 = __fmul_rn(__fadd_rn(vv.x, (float)x), 0.78125f);
        float c2 = __fmul_rn(__fadd_rn(vv.y, (float)y), 0.78125f);
        rx[q] = c0; ry[q] = c1; rz[q] = c2;
        vflag[q] = (vv.w > 0.5f) ? 1 : 0;
        cnt += vflag[q];
        int s = tid * 4 + q;
        int ob = (t ? OFF_TC : 0) + ((b * 2 + e) * 4096 + s) * 3;
        out[ob + 0] = c0; out[ob + 1] = c1; out[ob + 2] = c2;
    }

    int excl = blockScanExcl(cnt, wsum, tid);   // internal barriers fence sA2/sB2 reads
    int m = min(wsum[31], MAXV);

    for (int q = 0; q < 4; q++) {
        if (vflag[q]) {
            if (excl < MAXV) {
                cx[excl] = rx[q]; cy[excl] = ry[q]; cz[excl] = rz[q];
                spos[excl] = (unsigned short)(tid * 4 + q);
            }
            excl++;
        }
    }
    for (int i = tid; i < NBX * NBX * NBZ; i += NTH) binCnt[i] = 0;
    for (int q = 0; q < 4; q++) fullk[tid * 4 + q] = 0;
    __syncthreads();

    // ---- bins over compacted valid points ----
    for (int ci = tid; ci < m; ci += NTH) {
        int bx, by, bz;
        binCoords(cx[ci], cy[ci], cz[ci], invXY, invZ, bx, by, bz);
        atomicAdd(&binCnt[(bz * NBX + by) * NBX + bx], 1u);
    }
    __syncthreads();
    {
        int base8 = tid * 8;
        int loc[8]; int s = 0;
        for (int k2 = 0; k2 < 8; k2++) { loc[k2] = s; s += (int)binCnt[base8 + k2]; }
        int ex = blockScanExcl(s, wsum, tid);
        for (int k2 = 0; k2 < 8; k2++) binStart[base8 + k2] = (unsigned)(ex + loc[k2]);
    }
    __syncthreads();
    for (int i = tid; i < NBX * NBX * NBZ; i += NTH) binCnt[i] = 0;
    __syncthreads();
    for (int ci = tid; ci < m; ci += NTH) {
        int bx, by, bz;
        binCoords(cx[ci], cy[ci], cz[ci], invXY, invZ, bx, by, bz);
        int bb = (bz * NBX + by) * NBX + bx;
        unsigned off = atomicAdd(&binCnt[bb], 1u);
        binPts[binStart[bb] + off] = (unsigned short)ci;
    }
    __syncthreads();

    // ---- ONE-PASS earlier-neighbor list build ----
    if (tid == 0) remaining = 0;
    __syncthreads();
    {
        int undec = 0;
        for (int ci = tid; ci < m; ci += NTH) {
            float px = cx[ci], py = cy[ci], pz = cz[ci];
            int bx, by, bz;
            binCoords(px, py, pz, invXY, invZ, bx, by, bz);
            int nc = 0;
            #pragma unroll
            for (int dzb = -1; dzb <= 1; dzb++) {
                int Z = bz + dzb;
                if (Z < 0 || Z >= NBZ) continue;
                #pragma unroll
                for (int dyb = -1; dyb <= 1; dyb++) {
                    int Y = by + dyb;
                    if (Y < 0 || Y >= NBX) continue;
                    #pragma unroll
                    for (int dxb = -1; dxb <= 1; dxb++) {
                        int X = bx + dxb;
                        if (X < 0 || X >= NBX) continue;
                        int bb = (Z * NBX + Y) * NBX + X;
                        unsigned st = binStart[bb], cn = binCnt[bb];
                        for (unsigned p = 0; p < cn; p++) {
                            int a = binPts[st + p];
                            if (a < ci) {
                                float d2 = dist2(px, py, pz, cx[a], cy[a], cz[a]);
                                if (d2 < dd && nc < NNCAP)
                                    nbr[ci * NNCAP + nc++] = (unsigned short)a;
                            }
                        }
                    }
                }
            }
            nbrCnt[ci] = (unsigned char)nc;
            int st0 = (nc == 0) ? 1 : 0;
            state[ci] = (unsigned char)st0;
            undec += (st0 == 0);
        }
        if (undec) atomicAdd(&remaining, undec);
    }
    __syncthreads();

    // ---- wave NMS resolution (exact sequential semantics) ----
    while (true) {
        if (remaining <= 0) break;
        int dec = 0;
        for (int ci = tid; ci < m; ci += NTH) {
            if (state[ci] == 0) {
                int nc = nbrCnt[ci];
                bool anyK = false, allS = true;
                for (int k2 = 0; k2 < nc; k2++) {
                    unsigned char s2 = state[nbr[ci * NNCAP + k2]];
                    anyK |= (s2 == 1);
                    allS &= (s2 == 2);
                }
                if (anyK) { state[ci] = 2; dec++; }
                else if (allS) { state[ci] = 1; dec++; }
            }
        }
        if (dec) atomicSub(&remaining, dec);
        __syncthreads();
    }

    // ---- scatter keep into full mask ----
    for (int ci = tid; ci < m; ci += NTH)
        fullk[spos[ci]] = (state[ci] == 1) ? 1 : 0;

    // ---- order-preserving compaction of kept -> global scratch ----
    {
        int base2 = tid * 2;
        int k0 = (base2 < m) ? (state[base2] == 1) : 0;
        int k1 = (base2 + 1 < m) ? (state[base2 + 1] == 1) : 0;
        int ex2 = blockScanExcl(k0 + k1, wsum, tid);   // barrier also fences fullk scatter
        int kc = wsum[31];
        int gb = prob * 2048;
        if (k0) {
            g_kx[gb + ex2] = cx[base2]; g_ky[gb + ex2] = cy[base2];
            g_kz[gb + ex2] = cz[base2]; g_kpos[gb + ex2] = spos[base2];
            ex2++;
        }
        if (k1) {
            g_kx[gb + ex2] = cx[base2 + 1]; g_ky[gb + ex2] = cy[base2 + 1];
            g_kz[gb + ex2] = cz[base2 + 1]; g_kpos[gb + ex2] = spos[base2 + 1];
        }
        if (tid == 0) g_kcnt[prob] = kc;
    }

    // ---- write keep mask ----
    int kb = (t ? OFF_KT : OFF_KP) + (b * 2 + e) * 4096;
    for (int q = 0; q < 4; q++) {
        int s = tid * 4 + q;
        out[kb + s] = (float)fullk[s];
    }
}

// ---------------------------------------------------------------------------
// Kernel D (8 blocks): matching over precompacted kept lists -> tp/fp/fn
// ---------------------------------------------------------------------------
__global__ void __launch_bounds__(1024) k_match(float* __restrict__ out)
{
    extern __shared__ unsigned char sm[];
    float* cpx = (float*)sm;
    float* cpy = (float*)(sm + 8 * 1024);
    float* cpz = (float*)(sm + 16 * 1024);
    float* ctx = (float*)(sm + 24 * 1024);
    float* cty = (float*)(sm + 32 * 1024);
    float* ctz = (float*)(sm + 40 * 1024);
    unsigned short* ppos = (unsigned short*)(sm + 48 * 1024);
    unsigned short* tpos = (unsigned short*)(sm + 52 * 1024);
    unsigned int* binCnt = (unsigned int*)(sm + 56 * 1024);
    unsigned int* binStart = (unsigned int*)(sm + 88 * 1024);
    unsigned short* binPts = (unsigned short*)(sm + 120 * 1024);
    unsigned char* candCnt = (unsigned char*)(sm + 124 * 1024);
    unsigned short* cand = (unsigned short*)(sm + 126 * 1024);
    unsigned char* tpF = (unsigned char*)(sm + 174 * 1024);
    unsigned char* mtF = (unsigned char*)(sm + 178 * 1024);
    unsigned int* taken = (unsigned int*)(sm + 182 * 1024);
    unsigned int* minIdx = (unsigned int*)(sm + 56 * 1024);   // alias binCnt
    unsigned char* finP = (unsigned char*)(sm + 88 * 1024);   // alias binStart

    __shared__ int wsum[32];
    __shared__ int remaining;

    const int tid = threadIdx.x;
    const int be = blockIdx.x;
    const int b = be >> 1, e = be & 1;
    const float de = (e == 0) ? (float)(0.74 * 1.4) : (float)(0.528 * 1.4);
    const float dd = __fmul_rn(de, de);
    const float cellXY = fmaxf(de, 1.02f);
    const float invXY = 1.0f / cellXY;
    const float invZ = 1.0f / 1.3125f;

    const int kpBase = OFF_KP + (b * 2 + e) * 4096;
    const int ktBase = OFF_KT + (b * 2 + e) * 4096;
    const int pP = be, pT = 8 + be;

    const int KP = min(g_kcnt[pP], 2048);
    const int KT = min(g_kcnt[pT], 2048);

    // ---- load precompacted kept lists (coalesced, 2/thread) ----
    for (int i = tid; i < KP; i += NTH) {
        cpx[i] = g_kx[pP * 2048 + i];
        cpy[i] = g_ky[pP * 2048 + i];
        cpz[i] = g_kz[pP * 2048 + i];
        ppos[i] = g_kpos[pP * 2048 + i];
    }
    for (int i = tid; i < KT; i += NTH) {
        ctx[i] = g_kx[pT * 2048 + i];
        cty[i] = g_ky[pT * 2048 + i];
        ctz[i] = g_kz[pT * 2048 + i];
        tpos[i] = g_kpos[pT * 2048 + i];
    }
    for (int i = tid; i < NBX * NBX * NBZ; i += NTH) binCnt[i] = 0;
    if (tid < 64) taken[tid] = 0u;
    if (tid == 0) remaining = 0;
    for (int q = 0; q < 4; q++) { tpF[tid * 4 + q] = 0; mtF[tid * 4 + q] = 0; }
    __syncthreads();

    // ---- bin kept targets ----
    for (int ci = tid; ci < KT; ci += NTH) {
        int bx, by, bz;
        binCoords(ctx[ci], cty[ci], ctz[ci], invXY, invZ, bx, by, bz);
        atomicAdd(&binCnt[(bz * NBX + by) * NBX + bx], 1u);
    }
    __syncthreads();
    {
        int base8 = tid * 8;
        int loc[8]; int s = 0;
        for (int k2 = 0; k2 < 8; k2++) { loc[k2] = s; s += (int)binCnt[base8 + k2]; }
        int ex = blockScanExcl(s, wsum, tid);
        for (int k2 = 0; k2 < 8; k2++) binStart[base8 + k2] = (unsigned)(ex + loc[k2]);
    }
    __syncthreads();
    for (int i = tid; i < NBX * NBX * NBZ; i += NTH) binCnt[i] = 0;
    __syncthreads();
    for (int ci = tid; ci < KT; ci += NTH) {
        int bx, by, bz;
        binCoords(ctx[ci], cty[ci], ctz[ci], invXY, invZ, bx, by, bz);
        int bb = (bz * NBX + by) * NBX + bx;
        unsigned off = atomicAdd(&binCnt[bb], 1u);
        binPts[binStart[bb] + off] = (unsigned short)ci;
    }
    __syncthreads();

    // ---- build per-pred sorted candidate lists ----
    for (int ci = tid; ci < KP; ci += NTH) {
        float px = cpx[ci], py = cpy[ci], pz = cpz[ci];
        int bx, by, bz;
        binCoords(px, py, pz, invXY, invZ, bx, by, bz);
        unsigned short* cl = cand + ci * CAP;
        int nc = 0;
        #pragma unroll
        for (int dzb = -1; dzb <= 1; dzb++) {
            int Z = bz + dzb;
            if (Z < 0 || Z >= NBZ) continue;
            #pragma unroll
            for (int dyb = -1; dyb <= 1; dyb++) {
                int Y = by + dyb;
                if (Y < 0 || Y >= NBX) continue;
                #pragma unroll
                for (int dxb = -1; dxb <= 1; dxb++) {
                    int X = bx + dxb;
                    if (X < 0 || X >= NBX) continue;
                    int bb = (Z * NBX + Y) * NBX + X;
                    unsigned st = binStart[bb], cn = binCnt[bb];
                    for (unsigned p = 0; p < cn; p++) {
                        int a = binPts[st + p];
                        float d2 = dist2(px, py, pz, ctx[a], cty[a], ctz[a]);
                        if (d2 < dd) {
                            if (nc < CAP) {
                                int k2 = nc;
                                while (k2 > 0 && cl[k2 - 1] > a) { cl[k2] = cl[k2 - 1]; k2--; }
                                cl[k2] = (unsigned short)a;
                                nc++;
                            } else if (a < cl[CAP - 1]) {
                                int k2 = CAP - 1;
                                while (k2 > 0 && cl[k2 - 1] > a) { cl[k2] = cl[k2 - 1]; k2--; }
                                cl[k2] = (unsigned short)a;
                            }
                        }
                    }
                }
            }
        }
        candCnt[ci] = (unsigned char)nc;
    }
    __syncthreads();     // bins dead; finP aliases binStart

    // pre-finalize preds with no candidates
    {
        int act = 0;
        for (int i = tid; i < KP; i += NTH) {
            int a = (candCnt[i] > 0) ? 1 : 0;
            finP[i] = (unsigned char)(1 - a);
            act += a;
        }
        if (act) atomicAdd(&remaining, act);
    }
    __syncthreads();

    // ---- wave-parallel greedy resolution (exact sequential semantics) ----
    while (true) {
        if (remaining <= 0) break;
        for (int t2 = tid; t2 < KT; t2 += NTH) minIdx[t2] = 0x7FFFFFFFu;
        __syncthreads();
        for (int i = tid; i < KP; i += NTH) {
            if (!finP[i]) {
                int nc = candCnt[i];
                const unsigned short* cl = cand + i * CAP;
                for (int k2 = 0; k2 < nc; k2++)
                    atomicMin(&minIdx[cl[k2]], (unsigned)i);
            }
        }
        __syncthreads();
        for (int i = tid; i < KP; i += NTH) {
            if (!finP[i]) {
                int nc = candCnt[i];
                const unsigned short* cl = cand + i * CAP;
                bool ok = true;
                for (int k2 = 0; k2 < nc; k2++)
                    if (minIdx[cl[k2]] < (unsigned)i) { ok = false; break; }
                if (ok) {
                    for (int k2 = 0; k2 < nc; k2++) {
                        int j = cl[k2];
                        if (!((taken[j >> 5] >> (j & 31)) & 1u)) {
                            atomicOr(&taken[j >> 5], 1u << (j & 31));
                            tpF[ppos[i]] = 1;
                            mtF[tpos[j]] = 1;
                            break;
                        }
                    }
                    finP[i] = 1;
                    atomicSub(&remaining, 1);
                }
            }
        }
        __syncthreads();
    }

    // ---- write tp/fp/fn ----
    const int tpB = OFF_TP + (b * 2 + e) * 4096;
    const int fpB = OFF_FP + (b * 2 + e) * 4096;
    const int fnB = OFF_FN + (b * 2 + e) * 4096;
    for (int q = 0; q < 4; q++) {
        int s = tid * 4 + q;
        int tp = tpF[s];
        int kp = (out[kpBase + s] > 0.5f) ? 1 : 0;
        int kt = (out[ktBase + s] > 0.5f) ? 1 : 0;
        out[tpB + s] = (float)tp;
        out[fpB + s] = (kp && !tp) ? 1.0f : 0.0f;
        out[fnB + s] = (kt && !mtF[s]) ? 1.0f : 0.0f;
    }
}

// ---------------------------------------------------------------------------
extern "C" void kernel_launch(void* const* d_in, const int* in_sizes, int n_in,
                              void* d_out, int out_size)
{
    const float* pred = (const float*)d_in[0];
    const float* targ = (const float*)d_in[1];
    float* out = (float*)d_out;

    cudaFuncSetAttribute(k_nms, cudaFuncAttributeMaxDynamicSharedMemorySize, 168 * 1024);
    cudaFuncSetAttribute(k_match, cudaFuncAttributeMaxDynamicSharedMemorySize, 184 * 1024);

    k_sortA<<<64, NTH, 8 * 1024>>>(pred, targ);
    k_sortB<<<32, NTH, 16 * 1024>>>();
    k_nms<<<16, NTH, 168 * 1024>>>(pred, targ, out);
    k_match<<<8, NTH, 184 * 1024>>>(out);
}

// round 8
// speedup vs baseline: 5.0136x; 1.0188x over previous
#include <cuda_runtime.h>
#include <cstdint>

#define NPTS 4096
#define NTH  1024

// d_out float32 layout:
//   Pc [4][2][4096][3] @0, Tc @98304, keepP @196608, keepT @229376,
//   tp @262144, fp @294912, fn @327680
#define OFF_TC 98304
#define OFF_KP 196608
#define OFF_KT 229376
#define OFF_TP 262144
#define OFF_FP 294912
#define OFF_FN 327680

#define NBX 32
#define NBZ 8
#define CAP 12
#define NNCAP 16
#define MAXV 2048

__device__ unsigned long long g_run0[16 * 4096];
__device__ unsigned long long g_run1[16 * 4096];
// per-half compacted valid points (sorted order preserved)
__device__ float g_vx[16 * 4096];
__device__ float g_vy[16 * 4096];
__device__ float g_vz[16 * 4096];
__device__ unsigned short g_vs[16 * 4096];   // sorted position 0..4095
__device__ int g_vcnt[32];
// NMS-kept compact lists per problem
__device__ float g_kx[16 * 2048];
__device__ float g_ky[16 * 2048];
__device__ float g_kz[16 * 2048];
__device__ unsigned short g_kpos[16 * 2048];
__device__ int g_kcnt[16];

__device__ __forceinline__ float dist2(float ax, float ay, float az,
                                       float bx, float by, float bz) {
    float dx = __fadd_rn(ax, -bx);
    float dy = __fadd_rn(ay, -by);
    float dz = __fadd_rn(az, -bz);
    return __fadd_rn(__fadd_rn(__fmul_rn(dx, dx), __fmul_rn(dy, dy)),
                     __fmul_rn(dz, dz));
}

__device__ __forceinline__ int clampi(int v, int lo, int hi) {
    return v < lo ? lo : (v > hi ? hi : v);
}

__device__ __forceinline__ void binCoords(float x, float y, float z,
                                          float invXY, float invZ,
                                          int& bx, int& by, int& bz) {
    bx = clampi((int)floorf(__fmul_rn(__fadd_rn(x, 4.5f), invXY)), 0, NBX - 1);
    by = clampi((int)floorf(__fmul_rn(__fadd_rn(y, 4.5f), invXY)), 0, NBX - 1);
    bz = clampi((int)floorf(__fmul_rn(__fadd_rn(z, 4.0f), invZ)),  0, NBZ - 1);
}

__device__ __forceinline__ int blockScanExcl(int cnt, int* wsum, int tid) {
    int lane = tid & 31, wid = tid >> 5;
    int v = cnt;
    for (int o = 1; o < 32; o <<= 1) {
        int nn = __shfl_up_sync(0xFFFFFFFFu, v, o);
        if (lane >= o) v += nn;
    }
    if (lane == 31) wsum[wid] = v;
    __syncthreads();
    if (wid == 0) {
        int w = wsum[lane];
        for (int o = 1; o < 32; o <<= 1) {
            int nn = __shfl_up_sync(0xFFFFFFFFu, w, o);
            if (lane >= o) w += nn;
        }
        wsum[lane] = w;
    }
    __syncthreads();
    return v - cnt + (wid ? wsum[wid - 1] : 0);
}

// ---------------------------------------------------------------------------
// Kernel A (64 blocks): sort 1024-key runs -> g_run0
// ---------------------------------------------------------------------------
__global__ void __launch_bounds__(1024) k_sortA(const float* __restrict__ pred,
                                                const float* __restrict__ targ)
{
    extern __shared__ unsigned char sm[];
    unsigned long long* s = (unsigned long long*)sm;   // [1024]
    const int tid = threadIdx.x;
    const int bi = blockIdx.x;
    const int prob = bi >> 2;
    const int quarter = bi & 3;
    const int t = prob >> 3;
    const int be = prob & 7;
    const int b = be >> 1;
    const int e = be & 1;
    const float* in = (t == 0) ? pred : targ;

    int n = quarter * 1024 + tid;
    int z = n >> 10, x = (n >> 5) & 31, y = n & 31;
    int base = ((((b * 32 + x) * 32 + y) * 4 + z) * 8) + e * 4;
    float conf = in[base + 3];
    unsigned u = __float_as_uint(conf);
    u = (u & 0x80000000u) ? ~u : (u | 0x80000000u);
    unsigned long long v = (((unsigned long long)(~u)) << 32) | (unsigned)n;

    for (int k = 2; k <= 1024; k <<= 1) {
        bool up = ((tid & k) == 0);
        for (int j = k >> 1; j > 0; j >>= 1) {
            unsigned long long p;
            if (j >= 32) {
                s[tid] = v;
                __syncthreads();
                p = s[tid ^ j];
                __syncthreads();
            } else {
                p = __shfl_xor_sync(0xFFFFFFFFu, v, j);
            }
            bool lower = ((tid & j) == 0);
            bool kmin = (lower == up);
            unsigned long long mn = v < p ? v : p;
            unsigned long long mx = v < p ? p : v;
            v = kmin ? mn : mx;
        }
    }
    g_run0[prob * 4096 + quarter * 1024 + tid] = v;
}

// ---------------------------------------------------------------------------
// Kernel B (32 blocks): merge 1024+1024 -> 2048 -> g_run1
// ---------------------------------------------------------------------------
__global__ void __launch_bounds__(1024) k_sortB()
{
    extern __shared__ unsigned char sm[];
    unsigned long long* sA = (unsigned long long*)sm;              // [1024]
    unsigned long long* sB = (unsigned long long*)(sm + 8 * 1024); // [1024]
    const int tid = threadIdx.x;
    const int prob = blockIdx.x >> 1;
    const int half = blockIdx.x & 1;
    const unsigned long long* src = g_run0 + prob * 4096 + half * 2048;
    sA[tid] = src[tid];
    sB[tid] = src[1024 + tid];
    __syncthreads();

    int diag = tid * 2;
    int lo = diag > 1024 ? diag - 1024 : 0;
    int hi = diag < 1024 ? diag : 1024;
    while (lo < hi) {
        int mid = (lo + hi) >> 1;
        if (sA[mid] < sB[diag - 1 - mid]) lo = mid + 1; else hi = mid;
    }
    int ai = lo, bj = diag - lo;
    unsigned long long* dst = g_run1 + prob * 4096 + half * 2048;
    #pragma unroll
    for (int r = 0; r < 2; r++) {
        bool takeA = (bj >= 1024) || (ai < 1024 && sA[ai] <= sB[bj]);
        dst[diag + r] = takeA ? sA[ai++] : sB[bj++];
    }
}

// ---------------------------------------------------------------------------
// Kernel C1 (32 blocks, 2/problem): merge-path half -> coords -> Pc/Tc
//   + per-half order-preserving valid compaction -> g_v*
// ---------------------------------------------------------------------------
__global__ void __launch_bounds__(1024) k_coords(const float* __restrict__ pred,
                                                 const float* __restrict__ targ,
                                                 float* __restrict__ out)
{
    extern __shared__ unsigned char sm[];
    unsigned long long* sA2 = (unsigned long long*)sm;             // [2048] 16KB
    unsigned long long* sB2 = (unsigned long long*)(sm + 16 * 1024);
    __shared__ int wsum[32];

    const int tid = threadIdx.x;
    const int bi = blockIdx.x;
    const int prob = bi >> 1;
    const int half = bi & 1;
    const int t = prob >> 3;
    const int be = prob & 7;
    const int b = be >> 1;
    const int e = be & 1;
    const float* in = (t == 0) ? pred : targ;

    {
        const unsigned long long* src = g_run1 + prob * 4096;
        sA2[tid] = src[tid];
        sA2[1024 + tid] = src[1024 + tid];
        sB2[tid] = src[2048 + tid];
        sB2[1024 + tid] = src[3072 + tid];
    }
    __syncthreads();

    // merge-path: this thread produces sorted elements diag, diag+1
    const int diag = half * 2048 + tid * 2;
    int lo = diag > 2048 ? diag - 2048 : 0;
    int hi = diag < 2048 ? diag : 2048;
    while (lo < hi) {
        int mid = (lo + hi) >> 1;
        if (sA2[mid] < sB2[diag - 1 - mid]) lo = mid + 1; else hi = mid;
    }
    int ai = lo, bj = diag - lo;
    unsigned long long myk[2];
    #pragma unroll
    for (int r = 0; r < 2; r++) {
        bool takeA = (bj >= 2048) || (ai < 2048 && sA2[ai] <= sB2[bj]);
        myk[r] = takeA ? sA2[ai++] : sB2[bj++];
    }

    // coords + write Pc/Tc + valid flags
    float rx[2], ry[2], rz[2];
    int vf[2]; int cnt = 0;
    #pragma unroll
    for (int q = 0; q < 2; q++) {
        int n = (int)(myk[q] & 0xFFFFFFFFull);
        int z = n >> 10, x = (n >> 5) & 31, y = n & 31;
        int base = ((((b * 32 + x) * 32 + y) * 4 + z) * 8) + e * 4;
        float4 vv = *(const float4*)(in + base);
        float c0 = __fmul_rn(__fadd_rn(vv.z, (float)z), 0.75f);
        float c1 = __fmul_rn(__fadd_rn(vv.x, (float)x), 0.78125f);
        float c2 = __fmul_rn(__fadd_rn(vv.y, (float)y), 0.78125f);
        rx[q] = c0; ry[q] = c1; rz[q] = c2;
        vf[q] = (vv.w > 0.5f) ? 1 : 0;
        cnt += vf[q];
        int s = diag + q;
        int ob = (t ? OFF_TC : 0) + ((b * 2 + e) * 4096 + s) * 3;
        out[ob + 0] = c0; out[ob + 1] = c1; out[ob + 2] = c2;
    }

    int excl = blockScanExcl(cnt, wsum, tid);
    int gb = prob * 4096 + half * 2048;
    #pragma unroll
    for (int q = 0; q < 2; q++) {
        if (vf[q]) {
            g_vx[gb + excl] = rx[q];
            g_vy[gb + excl] = ry[q];
            g_vz[gb + excl] = rz[q];
            g_vs[gb + excl] = (unsigned short)(diag + q);
            excl++;
        }
    }
    if (tid == 0) g_vcnt[bi] = wsum[31];
}

// ---------------------------------------------------------------------------
// Kernel C2 (16 blocks): stitch halves -> bins -> neighbor lists -> wave NMS
//   -> keep masks in out; kept compact lists -> g_k*
// ---------------------------------------------------------------------------
__global__ void __launch_bounds__(1024) k_nms2(float* __restrict__ out)
{
    extern __shared__ unsigned char sm[];
    float* cx = (float*)sm;                                      // 8KB
    float* cy = (float*)(sm + 8 * 1024);
    float* cz = (float*)(sm + 16 * 1024);
    unsigned short* spos = (unsigned short*)(sm + 24 * 1024);    // 4KB
    unsigned char* fullk = (unsigned char*)(sm + 28 * 1024);     // 4KB
    unsigned short* nbr = (unsigned short*)(sm + 32 * 1024);     // 64KB
    unsigned int* binCnt = (unsigned int*)(sm + 96 * 1024);      // 32KB
    unsigned int* binStart = (unsigned int*)(sm + 128 * 1024);   // 32KB
    unsigned short* binPts = (unsigned short*)(sm + 160 * 1024); // 4KB
    unsigned char* nbrCnt = (unsigned char*)(sm + 164 * 1024);   // 2KB
    unsigned char* state = (unsigned char*)(sm + 166 * 1024);    // 2KB

    __shared__ int wsum[32];
    __shared__ int remaining;

    const int tid = threadIdx.x;
    const int prob = blockIdx.x;
    const int t = prob >> 3;
    const int be = prob & 7;
    const int b = be >> 1;
    const int e = be & 1;
    const float de = (e == 0) ? (float)(0.74 * 1.4) : (float)(0.528 * 1.4);
    const float dd = __fmul_rn(de, de);
    const float cellXY = fmaxf(de, 1.02f);
    const float invXY = 1.0f / cellXY;
    const float invZ = 1.0f / 1.3125f;

    const int c0 = min(g_vcnt[prob * 2], MAXV);
    const int c1 = g_vcnt[prob * 2 + 1];
    const int m = min(c0 + c1, MAXV);
    const int gb = prob * 4096;

    // stitch halves (order-preserving: half0 then half1)
    for (int i = tid; i < c0; i += NTH) {
        cx[i] = g_vx[gb + i]; cy[i] = g_vy[gb + i]; cz[i] = g_vz[gb + i];
        spos[i] = g_vs[gb + i];
    }
    for (int i = tid; i < m - c0; i += NTH) {
        cx[c0 + i] = g_vx[gb + 2048 + i];
        cy[c0 + i] = g_vy[gb + 2048 + i];
        cz[c0 + i] = g_vz[gb + 2048 + i];
        spos[c0 + i] = g_vs[gb + 2048 + i];
    }
    for (int i = tid; i < NBX * NBX * NBZ; i += NTH) binCnt[i] = 0;
    for (int q = 0; q < 4; q++) fullk[tid * 4 + q] = 0;
    if (tid == 0) remaining = 0;
    __syncthreads();

    // ---- bins ----
    for (int ci = tid; ci < m; ci += NTH) {
        int bx, by, bz;
        binCoords(cx[ci], cy[ci], cz[ci], invXY, invZ, bx, by, bz);
        atomicAdd(&binCnt[(bz * NBX + by) * NBX + bx], 1u);
    }
    __syncthreads();
    {
        int base8 = tid * 8;
        int loc[8]; int s = 0;
        for (int k2 = 0; k2 < 8; k2++) { loc[k2] = s; s += (int)binCnt[base8 + k2]; }
        int ex = blockScanExcl(s, wsum, tid);
        for (int k2 = 0; k2 < 8; k2++) binStart[base8 + k2] = (unsigned)(ex + loc[k2]);
    }
    __syncthreads();
    for (int i = tid; i < NBX * NBX * NBZ; i += NTH) binCnt[i] = 0;
    __syncthreads();
    for (int ci = tid; ci < m; ci += NTH) {
        int bx, by, bz;
        binCoords(cx[ci], cy[ci], cz[ci], invXY, invZ, bx, by, bz);
        int bb = (bz * NBX + by) * NBX + bx;
        unsigned off = atomicAdd(&binCnt[bb], 1u);
        binPts[binStart[bb] + off] = (unsigned short)ci;
    }
    __syncthreads();

    // ---- one-pass earlier-neighbor lists ----
    {
        int undec = 0;
        for (int ci = tid; ci < m; ci += NTH) {
            float px = cx[ci], py = cy[ci], pz = cz[ci];
            int bx, by, bz;
            binCoords(px, py, pz, invXY, invZ, bx, by, bz);
            int nc = 0;
            #pragma unroll
            for (int dzb = -1; dzb <= 1; dzb++) {
                int Z = bz + dzb;
                if (Z < 0 || Z >= NBZ) continue;
                #pragma unroll
                for (int dyb = -1; dyb <= 1; dyb++) {
                    int Y = by + dyb;
                    if (Y < 0 || Y >= NBX) continue;
                    #pragma unroll
                    for (int dxb = -1; dxb <= 1; dxb++) {
                        int X = bx + dxb;
                        if (X < 0 || X >= NBX) continue;
                        int bb = (Z * NBX + Y) * NBX + X;
                        unsigned st = binStart[bb], cn = binCnt[bb];
                        for (unsigned p = 0; p < cn; p++) {
                            int a = binPts[st + p];
                            if (a < ci) {
                                float d2 = dist2(px, py, pz, cx[a], cy[a], cz[a]);
                                if (d2 < dd && nc < NNCAP)
                                    nbr[ci * NNCAP + nc++] = (unsigned short)a;
                            }
                        }
                    }
                }
            }
            nbrCnt[ci] = (unsigned char)nc;
            int st0 = (nc == 0) ? 1 : 0;
            state[ci] = (unsigned char)st0;
            undec += (st0 == 0);
        }
        if (undec) atomicAdd(&remaining, undec);
    }
    __syncthreads();

    // ---- wave NMS resolution (exact sequential semantics) ----
    while (true) {
        if (remaining <= 0) break;
        int dec = 0;
        for (int ci = tid; ci < m; ci += NTH) {
            if (state[ci] == 0) {
                int nc = nbrCnt[ci];
                bool anyK = false, allS = true;
                for (int k2 = 0; k2 < nc; k2++) {
                    unsigned char s2 = state[nbr[ci * NNCAP + k2]];
                    anyK |= (s2 == 1);
                    allS &= (s2 == 2);
                }
                if (anyK) { state[ci] = 2; dec++; }
                else if (allS) { state[ci] = 1; dec++; }
            }
        }
        if (dec) atomicSub(&remaining, dec);
        __syncthreads();
    }

    // ---- keep mask scatter ----
    for (int ci = tid; ci < m; ci += NTH)
        fullk[spos[ci]] = (state[ci] == 1) ? 1 : 0;

    // ---- order-preserving compaction of kept -> g_k* ----
    {
        int base2 = tid * 2;
        int k0 = (base2 < m) ? (state[base2] == 1) : 0;
        int k1 = (base2 + 1 < m) ? (state[base2 + 1] == 1) : 0;
        int ex2 = blockScanExcl(k0 + k1, wsum, tid);   // barrier fences fullk scatter too
        int kc = wsum[31];
        int kb2 = prob * 2048;
        if (k0) {
            g_kx[kb2 + ex2] = cx[base2]; g_ky[kb2 + ex2] = cy[base2];
            g_kz[kb2 + ex2] = cz[base2]; g_kpos[kb2 + ex2] = spos[base2];
            ex2++;
        }
        if (k1) {
            g_kx[kb2 + ex2] = cx[base2 + 1]; g_ky[kb2 + ex2] = cy[base2 + 1];
            g_kz[kb2 + ex2] = cz[base2 + 1]; g_kpos[kb2 + ex2] = spos[base2 + 1];
        }
        if (tid == 0) g_kcnt[prob] = kc;
    }

    // ---- write keep mask ----
    int kb = (t ? OFF_KT : OFF_KP) + (b * 2 + e) * 4096;
    for (int q = 0; q < 4; q++) {
        int s = tid * 4 + q;
        out[kb + s] = (float)fullk[s];
    }
}

// ---------------------------------------------------------------------------
// Kernel D (8 blocks): matching with active-list wave resolution
// ---------------------------------------------------------------------------
__global__ void __launch_bounds__(1024) k_match(float* __restrict__ out)
{
    extern __shared__ unsigned char sm[];
    float* cpx = (float*)sm;
    float* cpy = (float*)(sm + 8 * 1024);
    float* cpz = (float*)(sm + 16 * 1024);
    float* ctx = (float*)(sm + 24 * 1024);
    float* cty = (float*)(sm + 32 * 1024);
    float* ctz = (float*)(sm + 40 * 1024);
    unsigned short* ppos = (unsigned short*)(sm + 48 * 1024);
    unsigned short* tpos = (unsigned short*)(sm + 52 * 1024);
    unsigned int* binCnt = (unsigned int*)(sm + 56 * 1024);
    unsigned int* binStart = (unsigned int*)(sm + 88 * 1024);
    unsigned short* binPts = (unsigned short*)(sm + 120 * 1024);
    unsigned char* candCnt = (unsigned char*)(sm + 124 * 1024);
    unsigned short* cand = (unsigned short*)(sm + 126 * 1024);
    unsigned char* tpF = (unsigned char*)(sm + 174 * 1024);
    unsigned char* mtF = (unsigned char*)(sm + 178 * 1024);
    unsigned int* taken = (unsigned int*)(sm + 182 * 1024);
    unsigned int* minIdx = (unsigned int*)(sm + 56 * 1024);    // alias binCnt (8KB)
    unsigned short* actA = (unsigned short*)(sm + 88 * 1024);  // alias binStart
    unsigned short* actB = (unsigned short*)(sm + 92 * 1024);

    __shared__ int wsum[32];
    __shared__ int nact, nNext;

    const int tid = threadIdx.x;
    const int be = blockIdx.x;
    const int b = be >> 1, e = be & 1;
    const float de = (e == 0) ? (float)(0.74 * 1.4) : (float)(0.528 * 1.4);
    const float dd = __fmul_rn(de, de);
    const float cellXY = fmaxf(de, 1.02f);
    const float invXY = 1.0f / cellXY;
    const float invZ = 1.0f / 1.3125f;

    const int kpBase = OFF_KP + (b * 2 + e) * 4096;
    const int ktBase = OFF_KT + (b * 2 + e) * 4096;
    const int pP = be, pT = 8 + be;

    const int KP = min(g_kcnt[pP], 2048);
    const int KT = min(g_kcnt[pT], 2048);

    for (int i = tid; i < KP; i += NTH) {
        cpx[i] = g_kx[pP * 2048 + i];
        cpy[i] = g_ky[pP * 2048 + i];
        cpz[i] = g_kz[pP * 2048 + i];
        ppos[i] = g_kpos[pP * 2048 + i];
    }
    for (int i = tid; i < KT; i += NTH) {
        ctx[i] = g_kx[pT * 2048 + i];
        cty[i] = g_ky[pT * 2048 + i];
        ctz[i] = g_kz[pT * 2048 + i];
        tpos[i] = g_kpos[pT * 2048 + i];
    }
    for (int i = tid; i < NBX * NBX * NBZ; i += NTH) binCnt[i] = 0;
    if (tid < 64) taken[tid] = 0u;
    if (tid == 0) { nact = 0; nNext = 0; }
    for (int q = 0; q < 4; q++) { tpF[tid * 4 + q] = 0; mtF[tid * 4 + q] = 0; }
    __syncthreads();

    // ---- bin kept targets ----
    for (int ci = tid; ci < KT; ci += NTH) {
        int bx, by, bz;
        binCoords(ctx[ci], cty[ci], ctz[ci], invXY, invZ, bx, by, bz);
        atomicAdd(&binCnt[(bz * NBX + by) * NBX + bx], 1u);
    }
    __syncthreads();
    {
        int base8 = tid * 8;
        int loc[8]; int s = 0;
        for (int k2 = 0; k2 < 8; k2++) { loc[k2] = s; s += (int)binCnt[base8 + k2]; }
        int ex = blockScanExcl(s, wsum, tid);
        for (int k2 = 0; k2 < 8; k2++) binStart[base8 + k2] = (unsigned)(ex + loc[k2]);
    }
    __syncthreads();
    for (int i = tid; i < NBX * NBX * NBZ; i += NTH) binCnt[i] = 0;
    __syncthreads();
    for (int ci = tid; ci < KT; ci += NTH) {
        int bx, by, bz;
        binCoords(ctx[ci], cty[ci], ctz[ci], invXY, invZ, bx, by, bz);
        int bb = (bz * NBX + by) * NBX + bx;
        unsigned off = atomicAdd(&binCnt[bb], 1u);
        binPts[binStart[bb] + off] = (unsigned short)ci;
    }
    __syncthreads();

    // ---- per-pred sorted candidate lists ----
    for (int ci = tid; ci < KP; ci += NTH) {
        float px = cpx[ci], py = cpy[ci], pz = cpz[ci];
        int bx, by, bz;
        binCoords(px, py, pz, invXY, invZ, bx, by, bz);
        unsigned short* cl = cand + ci * CAP;
        int nc = 0;
        #pragma unroll
        for (int dzb = -1; dzb <= 1; dzb++) {
            int Z = bz + dzb;
            if (Z < 0 || Z >= NBZ) continue;
            #pragma unroll
            for (int dyb = -1; dyb <= 1; dyb++) {
                int Y = by + dyb;
                if (Y < 0 || Y >= NBX) continue;
                #pragma unroll
                for (int dxb = -1; dxb <= 1; dxb++) {
                    int X = bx + dxb;
                    if (X < 0 || X >= NBX) continue;
                    int bb = (Z * NBX + Y) * NBX + X;
                    unsigned st = binStart[bb], cn = binCnt[bb];
                    for (unsigned p = 0; p < cn; p++) {
                        int a = binPts[st + p];
                        float d2 = dist2(px, py, pz, ctx[a], cty[a], ctz[a]);
                        if (d2 < dd) {
                            if (nc < CAP) {
                                int k2 = nc;
                                while (k2 > 0 && cl[k2 - 1] > a) { cl[k2] = cl[k2 - 1]; k2--; }
                                cl[k2] = (unsigned short)a;
                                nc++;
                            } else if (a < cl[CAP - 1]) {
                                int k2 = CAP - 1;
                                while (k2 > 0 && cl[k2 - 1] > a) { cl[k2] = cl[k2 - 1]; k2--; }
                                cl[k2] = (unsigned short)a;
                            }
                        }
                    }
                }
            }
        }
        candCnt[ci] = (unsigned char)nc;
    }
    __syncthreads();     // bins dead; actA/actB alias binStart region

    // ---- initial active list (preds with candidates) ----
    for (int i = tid; i < KP; i += NTH) {
        if (candCnt[i] > 0) {
            int p = atomicAdd(&nact, 1);
            actA[p] = (unsigned short)i;
        }
    }
    int parity = 0;

    // ---- active-list wave resolution (exact sequential semantics) ----
    while (true) {
        __syncthreads();
        int na = nact;
        if (na <= 0) break;
        const unsigned short* A = parity ? actB : actA;
        unsigned short* Bn = parity ? actA : actB;

        // targeted minIdx init (races benign: all write same value)
        for (int idx = tid; idx < na; idx += NTH) {
            int i = A[idx];
            int nc = candCnt[i];
            const unsigned short* cl = cand + i * CAP;
            for (int k2 = 0; k2 < nc; k2++) minIdx[cl[k2]] = 0x7FFFFFFFu;
        }
        if (tid == 0) nNext = 0;
        __syncthreads();
        for (int idx = tid; idx < na; idx += NTH) {
            int i = A[idx];
            int nc = candCnt[i];
            const unsigned short* cl = cand + i * CAP;
            for (int k2 = 0; k2 < nc; k2++)
                atomicMin(&minIdx[cl[k2]], (unsigned)i);
        }
        __syncthreads();
        for (int idx = tid; idx < na; idx += NTH) {
            int i = A[idx];
            int nc = candCnt[i];
            const unsigned short* cl = cand + i * CAP;
            bool ok = true;
            for (int k2 = 0; k2 < nc; k2++)
                if (minIdx[cl[k2]] < (unsigned)i) { ok = false; break; }
            if (ok) {
                for (int k2 = 0; k2 < nc; k2++) {
                    int j = cl[k2];
                    if (!((taken[j >> 5] >> (j & 31)) & 1u)) {
                        atomicOr(&taken[j >> 5], 1u << (j & 31));
                        tpF[ppos[i]] = 1;
                        mtF[tpos[j]] = 1;
                        break;
                    }
                }
            } else {
                int p = atomicAdd(&nNext, 1);
                Bn[p] = (unsigned short)i;
            }
        }
        __syncthreads();
        if (tid == 0) nact = nNext;
        parity ^= 1;
    }

    // ---- write tp/fp/fn ----
    const int tpB = OFF_TP + (b * 2 + e) * 4096;
    const int fpB = OFF_FP + (b * 2 + e) * 4096;
    const int fnB = OFF_FN + (b * 2 + e) * 4096;
    for (int q = 0; q < 4; q++) {
        int s = tid * 4 + q;
        int tp = tpF[s];
        int kp = (out[kpBase + s] > 0.5f) ? 1 : 0;
        int kt = (out[ktBase + s] > 0.5f) ? 1 : 0;
        out[tpB + s] = (float)tp;
        out[fpB + s] = (kp && !tp) ? 1.0f : 0.0f;
        out[fnB + s] = (kt && !mtF[s]) ? 1.0f : 0.0f;
    }
}

// ---------------------------------------------------------------------------
extern "C" void kernel_launch(void* const* d_in, const int* in_sizes, int n_in,
                              void* d_out, int out_size)
{
    const float* pred = (const float*)d_in[0];
    const float* targ = (const float*)d_in[1];
    float* out = (float*)d_out;

    cudaFuncSetAttribute(k_nms2, cudaFuncAttributeMaxDynamicSharedMemorySize, 168 * 1024);
    cudaFuncSetAttribute(k_match, cudaFuncAttributeMaxDynamicSharedMemorySize, 184 * 1024);

    k_sortA<<<64, NTH, 8 * 1024>>>(pred, targ);
    k_sortB<<<32, NTH, 16 * 1024>>>();
    k_coords<<<32, NTH, 32 * 1024>>>(pred, targ, out);
    k_nms2<<<16, NTH, 168 * 1024>>>(out);
    k_match<<<8, NTH, 184 * 1024>>>(out);
}